// round 11
// baseline (speedup 1.0000x reference)
#include <cuda_runtime.h>
#include <cuda_fp16.h>
#include <cstdint>
#include <math.h>

// Problem constants
#define B_SZ   4
#define S_SZ   8192
#define D_SZ   512
#define H_SZ   8
#define HD_SZ  64
#define N_TOK  (B_SZ * S_SZ)          // 32768
#define BH_SZ  (B_SZ * H_SZ)          // 32

// ---------------- scratch (static __device__, no allocations) ----------------
__device__ __half g_xh[(size_t)N_TOK * D_SZ];
__device__ __half g_xl[(size_t)N_TOK * D_SZ];
__device__ __half g_wt[4 * D_SZ * D_SZ];          // transposed weights, fp16
__device__ __half g_qh[(size_t)N_TOK * D_SZ];     // feature-mapped q, hi/lo
__device__ __half g_ql[(size_t)N_TOK * D_SZ];
__device__ __half g_kh[(size_t)N_TOK * D_SZ];     // feature-mapped k, hi/lo
__device__ __half g_kl[(size_t)N_TOK * D_SZ];
__device__ __half g_vh[(size_t)N_TOK * D_SZ];     // v, hi/lo
__device__ __half g_vl[(size_t)N_TOK * D_SZ];
__device__ __half g_ah[(size_t)N_TOK * D_SZ];
__device__ __half g_al[(size_t)N_TOK * D_SZ];
__device__ float  g_y[(size_t)N_TOK * D_SZ];
__device__ float  g_kv[BH_SZ * HD_SZ * HD_SZ];
__device__ float  g_ksum[BH_SZ * HD_SZ];

// ======================= helpers ==============================================
__device__ __forceinline__ uint32_t smem_u32(const void* p) {
    uint32_t a;
    asm("{ .reg .u64 t; cvta.to.shared.u64 t, %1; cvt.u32.u64 %0, t; }"
        : "=r"(a) : "l"(p));
    return a;
}
__device__ __forceinline__ void cpa16(uint32_t dst, const void* src) {
    asm volatile("cp.async.cg.shared.global [%0], [%1], 16;" :: "r"(dst), "l"(src));
}
#define CPA_COMMIT() asm volatile("cp.async.commit_group;" ::: "memory")
#define CPA_WAIT(n)  asm volatile("cp.async.wait_group %0;" :: "n"(n) : "memory")

#define LDSM4(r, addr)                                                          \
    asm volatile("ldmatrix.sync.aligned.m8n8.x4.shared.b16 {%0,%1,%2,%3}, [%4];"\
                 : "=r"((r)[0]), "=r"((r)[1]), "=r"((r)[2]), "=r"((r)[3])       \
                 : "r"(addr))
#define LDSM4T(r, addr)                                                         \
    asm volatile("ldmatrix.sync.aligned.m8n8.x4.trans.shared.b16 {%0,%1,%2,%3}, [%4];"\
                 : "=r"((r)[0]), "=r"((r)[1]), "=r"((r)[2]), "=r"((r)[3])       \
                 : "r"(addr))

// HMMA: D(16x8,f32) += A(16x16,f16,row) * B(16x8,f16,col)
__device__ __forceinline__ void mma16816(float* d, const uint32_t* a, const uint32_t* b) {
    asm volatile(
        "mma.sync.aligned.m16n8k16.row.col.f32.f16.f16.f32 "
        "{%0,%1,%2,%3}, {%4,%5,%6,%7}, {%8,%9}, {%0,%1,%2,%3};"
        : "+f"(d[0]), "+f"(d[1]), "+f"(d[2]), "+f"(d[3])
        : "r"(a[0]), "r"(a[1]), "r"(a[2]), "r"(a[3]), "r"(b[0]), "r"(b[1]));
}

__device__ __forceinline__ void split2h(float v, __half& h, __half& l) {
    h = __float2half(v);
    l = __float2half(v - __half2float(h));
}
__device__ __forceinline__ uint32_t packh2(__half a, __half b) {
    __half2 p = __halves2half2(a, b);
    return *(uint32_t*)&p;
}

// ======================= conversion kernels ===================================
// also zeroes the kv/ksum accumulators (merged zero_acc)
__global__ __launch_bounds__(256) void convert_x_kernel(const float* __restrict__ x)
{
    size_t i = (size_t)blockIdx.x * 256 + threadIdx.x;   // float4 index
    float4 v = ((const float4*)x)[i];
    __half h[4], l[4];
    split2h(v.x, h[0], l[0]); split2h(v.y, h[1], l[1]);
    split2h(v.z, h[2], l[2]); split2h(v.w, h[3], l[3]);
    *(uint2*)&g_xh[4 * i] = *(uint2*)h;
    *(uint2*)&g_xl[4 * i] = *(uint2*)l;
    if (i < BH_SZ * HD_SZ * HD_SZ) g_kv[i] = 0.f;
    if (i < BH_SZ * HD_SZ)         g_ksum[i] = 0.f;
}

// transpose 4 weights to fp16: Wt[w][n][k] = W_w[k][n]
__global__ void convert_w_kernel(const float* __restrict__ Wq, const float* __restrict__ Wk,
                                 const float* __restrict__ Wv, const float* __restrict__ Wo)
{
    __shared__ float tile[32][33];
    const int w = blockIdx.z;
    const float* W = (w == 0) ? Wq : (w == 1) ? Wk : (w == 2) ? Wv : Wo;
    int tx = threadIdx.x, ty = threadIdx.y;
    int k = blockIdx.y * 32 + ty;
    int n = blockIdx.x * 32 + tx;
    tile[ty][tx] = W[k * D_SZ + n];
    __syncthreads();
    int nn = blockIdx.x * 32 + ty;
    int kk = blockIdx.y * 32 + tx;
    float v = tile[tx][ty];
    size_t idx = (size_t)w * D_SZ * D_SZ + (size_t)nn * D_SZ + kk;
    g_wt[idx] = __float2half(v);
}

// ======================= tensor-core GEMM (mma.sync fp16, A-split) ============
// CTA tile 128x128, BK=32, 256 threads (8 warps, 4x2), warp tile 32x64.
// 2-stage cp.async pipeline; D = Ah*B + Al*B (A split fp16, B single fp16).
// MODE 0: fused QKV; q,k -> fp16 hi/lo (featmap), v -> fp16 hi/lo
// MODE 2: Wo (+bias, +resid) -> fp32
#define BKC     32
#define RSTRIDE 80           // bytes per smem row (32 fp16 + 16 pad)
#define A_BYTES (128 * RSTRIDE)
#define B_BYTES (128 * RSTRIDE)
#define AH_OFF  0
#define AL_OFF  (A_BYTES)
#define BH_OFF  (2 * A_BYTES)
#define STAGE_BYTES (2 * A_BYTES + B_BYTES)       // 30720
#define NSTAGE  2
#define NCHUNK  (D_SZ / BKC)                      // 16

template <int MODE>
__global__ __launch_bounds__(256, 2)
void gemm_tc(const __half* __restrict__ Ah, const __half* __restrict__ Al,
             const __half* __restrict__ Bh,
             const float* __restrict__ b0p, const float* __restrict__ b1p,
             const float* __restrict__ b2p, const float* __restrict__ resid,
             float* __restrict__ C0)
{
    extern __shared__ __align__(16) char dsm[];
    const uint32_t sb = smem_u32(dsm);

    const int t    = threadIdx.x;
    const int lane = t & 31;
    const int wid  = t >> 5;
    const int wm   = wid >> 1;          // 0..3  (32-row group)
    const int wn   = wid & 1;           // 0..1  (64-col group)
    const int m0   = blockIdx.y * 128;
    const int n0   = blockIdx.x * 128;

    float acc[2][8][4];
#pragma unroll
    for (int i = 0; i < 2; i++)
#pragma unroll
        for (int j = 0; j < 8; j++)
#pragma unroll
            for (int r = 0; r < 4; r++) acc[i][j][r] = 0.f;

    const uint32_t aoff = (uint32_t)(wm * 32 + (lane & 15)) * RSTRIDE
                        + ((lane >> 4) & 1) * 16;
    const uint32_t boff = (uint32_t)(wn * 64 + (lane & 7) + ((lane >> 4) & 1) * 8) * RSTRIDE
                        + ((lane >> 3) & 1) * 16;

    auto load_chunk = [&](int kc, int stage) {
        const uint32_t base = sb + stage * STAGE_BYTES;
        const size_t gkoff = (size_t)kc * BKC;
#pragma unroll
        for (int e = 0; e < 2; e++) {            // A: 128 rows x 4 parts = 512
            int id   = t + e * 256;
            int row  = id >> 2;
            int part = id & 3;
            uint32_t doff = row * RSTRIDE + part * 16;
            size_t   goff = (size_t)(m0 + row) * D_SZ + gkoff + part * 8;
            cpa16(base + AH_OFF + doff, Ah + goff);
            cpa16(base + AL_OFF + doff, Al + goff);
        }
#pragma unroll
        for (int e = 0; e < 2; e++) {            // B: 128 rows x 4 parts = 512
            int id   = t + e * 256;
            int row  = id >> 2;
            int part = id & 3;
            uint32_t doff = row * RSTRIDE + part * 16;
            size_t   goff = (size_t)(n0 + row) * D_SZ + gkoff + part * 8;
            cpa16(base + BH_OFF + doff, Bh + goff);
        }
        CPA_COMMIT();
    };

    auto compute_chunk = [&](int stage) {
        const uint32_t base = sb + stage * STAGE_BYTES;
        const uint32_t aH = base + AH_OFF + aoff;
        const uint32_t aL = base + AL_OFF + aoff;
        const uint32_t bH = base + BH_OFF + boff;
#pragma unroll
        for (int kk = 0; kk < 2; kk++) {
            const int cb = kk * 32;
            uint32_t fah[2][4], fal[2][4];
            LDSM4(fah[0], aH + cb);
            LDSM4(fah[1], aH + 16 * RSTRIDE + cb);
            LDSM4(fal[0], aL + cb);
            LDSM4(fal[1], aL + 16 * RSTRIDE + cb);
#pragma unroll
            for (int nh = 0; nh < 2; nh++) {
                const uint32_t bo2 = nh * 32 * RSTRIDE + cb;
                uint32_t fbh[2][4];
                LDSM4(fbh[0], bH + bo2);
                LDSM4(fbh[1], bH + bo2 + 16 * RSTRIDE);
#pragma unroll
                for (int mi = 0; mi < 2; mi++)
#pragma unroll
                    for (int nj = 0; nj < 4; nj++)
                        mma16816(acc[mi][nh * 4 + nj], fah[mi], &fbh[nj >> 1][(nj & 1) * 2]);
#pragma unroll
                for (int mi = 0; mi < 2; mi++)
#pragma unroll
                    for (int nj = 0; nj < 4; nj++)
                        mma16816(acc[mi][nh * 4 + nj], fal[mi], &fbh[nj >> 1][(nj & 1) * 2]);
            }
        }
    };

    load_chunk(0, 0);
    for (int c = 0; c < NCHUNK; c++) {
        if (c + 1 < NCHUNK) {
            load_chunk(c + 1, (c + 1) & 1);
            CPA_WAIT(1);
        } else {
            CPA_WAIT(0);
        }
        __syncthreads();
        compute_chunk(c & 1);
        __syncthreads();
    }

    // ---- epilogue ----
    const int wsel = (MODE == 0) ? (n0 >> 9) : 0;
    const float* bias = (MODE == 0) ? ((wsel == 0) ? b0p : (wsel == 1) ? b1p : b2p) : b0p;
    const int ncol0 = (MODE == 0) ? (n0 & 511) : n0;

    const int g  = lane >> 2;
    const int tg = lane & 3;
#pragma unroll
    for (int mi = 0; mi < 2; mi++) {
#pragma unroll
        for (int half = 0; half < 2; half++) {
            int row = m0 + wm * 32 + mi * 16 + g + half * 8;
            const float* Rrow = (MODE == 2) ? (resid + (size_t)row * D_SZ) : nullptr;
#pragma unroll
            for (int nj = 0; nj < 8; nj++) {
                int col = ncol0 + wn * 64 + nj * 8 + tg * 2;
                float v0 = acc[mi][nj][half * 2 + 0] + bias[col];
                float v1 = acc[mi][nj][half * 2 + 1] + bias[col + 1];
                if (MODE == 0) {
                    if (wsel < 2) {   // feature map for q and k
                        v0 = (v0 > 0.f) ? (v0 + 1.f) : __expf(v0);
                        v1 = (v1 > 0.f) ? (v1 + 1.f) : __expf(v1);
                    }
                    size_t idx = (size_t)row * D_SZ + col;
                    __half h0, l0, h1, l1;
                    split2h(v0, h0, l0);
                    split2h(v1, h1, l1);
                    uint32_t hw = packh2(h0, h1), lw = packh2(l0, l1);
                    if (wsel == 0) {
                        *(uint32_t*)&g_qh[idx] = hw;
                        *(uint32_t*)&g_ql[idx] = lw;
                    } else if (wsel == 1) {
                        *(uint32_t*)&g_kh[idx] = hw;
                        *(uint32_t*)&g_kl[idx] = lw;
                    } else {
                        *(uint32_t*)&g_vh[idx] = hw;
                        *(uint32_t*)&g_vl[idx] = lw;
                    }
                } else {
                    v0 += Rrow[col];
                    v1 += Rrow[col + 1];
                    *(float2*)&C0[(size_t)row * D_SZ + col] = make_float2(v0, v1);
                }
            }
        }
    }
}

// ---------------- kv = K^T V per (b,h) via HMMA, plus k_sum --------------------
#define KVSTRIDE 144                       // bytes per smem row (64 fp16 + 8 pad)
__global__ __launch_bounds__(256)
void kv_kernel()
{
    __shared__ __half skh[64 * 72];
    __shared__ __half skl[64 * 72];
    __shared__ __half svh[64 * 72];
    __shared__ __half svl[64 * 72];

    const int bh    = blockIdx.y;
    const int chunk = blockIdx.x;          // 256-row chunk
    const int b = bh >> 3, h = bh & 7;
    const size_t tok0 = (size_t)b * S_SZ + chunk * 256;

    const int t    = threadIdx.x;
    const int lane = t & 31;
    const int wid  = t >> 5;
    const int d0   = (wid >> 1) * 16;
    const int m0   = (wid & 1) * 32;

    const uint32_t pkh = smem_u32(skh), pkl = smem_u32(skl);
    const uint32_t pvh = smem_u32(svh), pvl = smem_u32(svl);

    const uint32_t aoff = ((lane & 7) + ((lane >> 4) & 1) * 8) * KVSTRIDE
                        + d0 * 2 + ((lane >> 3) & 1) * 16;
    const uint32_t boff = ((lane & 7) + ((lane >> 3) & 1) * 8) * KVSTRIDE
                        + m0 * 2 + ((lane >> 4) & 1) * 16;

    float acc[4][4];
#pragma unroll
    for (int j = 0; j < 4; j++)
#pragma unroll
        for (int r = 0; r < 4; r++) acc[j][r] = 0.f;
    float ksl = 0.f;
    const int kcol  = t & 63;
    const int krow0 = (t >> 6) * 16;

    for (int it = 0; it < 4; it++) {       // 4 tiles of 64 rows
#pragma unroll
        for (int e = 0; e < 2; e++) {
            int id   = t + e * 256;
            int row  = id >> 3;
            int part = id & 7;
            uint32_t doff = row * KVSTRIDE + part * 16;
            size_t   goff = (tok0 + it * 64 + row) * D_SZ + h * HD_SZ + part * 8;
            cpa16(pkh + doff, g_kh + goff);
            cpa16(pkl + doff, g_kl + goff);
            cpa16(pvh + doff, g_vh + goff);
            cpa16(pvl + doff, g_vl + goff);
        }
        CPA_COMMIT();
        CPA_WAIT(0);
        __syncthreads();

#pragma unroll
        for (int r = 0; r < 16; r++) {
            int rr = krow0 + r;
            ksl += __half2float(skh[rr * 72 + kcol]) + __half2float(skl[rr * 72 + kcol]);
        }

#pragma unroll
        for (int ks = 0; ks < 4; ks++) {
            const uint32_t so = ks * 16 * KVSTRIDE;
            uint32_t akh[4], akl[4], bvh0[4], bvh1[4], bvl0[4], bvl1[4];
            LDSM4T(akh, pkh + aoff + so);
            LDSM4T(akl, pkl + aoff + so);
            LDSM4T(bvh0, pvh + boff + so);
            LDSM4T(bvh1, pvh + boff + so + 32);
            LDSM4T(bvl0, pvl + boff + so);
            LDSM4T(bvl1, pvl + boff + so + 32);
#pragma unroll
            for (int j = 0; j < 4; j++) {
                const uint32_t* bh2 = (j < 2) ? &bvh0[(j & 1) * 2] : &bvh1[(j & 1) * 2];
                const uint32_t* bl2 = (j < 2) ? &bvl0[(j & 1) * 2] : &bvl1[(j & 1) * 2];
                mma16816(acc[j], akh, bh2);
                mma16816(acc[j], akh, bl2);
                mma16816(acc[j], akl, bh2);
            }
        }
        __syncthreads();
    }

    float* kvdst = g_kv + bh * (HD_SZ * HD_SZ);
    const int g  = lane >> 2;
    const int tg = lane & 3;
#pragma unroll
    for (int j = 0; j < 4; j++) {
        int col = m0 + j * 8 + tg * 2;
        atomicAdd(&kvdst[(d0 + g) * HD_SZ + col],         acc[j][0]);
        atomicAdd(&kvdst[(d0 + g) * HD_SZ + col + 1],     acc[j][1]);
        atomicAdd(&kvdst[(d0 + g + 8) * HD_SZ + col],     acc[j][2]);
        atomicAdd(&kvdst[(d0 + g + 8) * HD_SZ + col + 1], acc[j][3]);
    }
    atomicAdd(&g_ksum[bh * HD_SZ + kcol], ksl);
}

// ---------------- out = (q @ kv) / max(q . ksum, 1e-6) via HMMA ----------------
// grid: (S/64 tiles, 32 bh). 256 threads = 8 warps (4 token-groups x 2 col-groups).
// out[64 tok, 64 cols] = qh*kvh + ql*kvh + qh*kvl ; normalizer fp32 from qh+ql.
__global__ __launch_bounds__(256)
void attn_kernel()
{
    __shared__ __half sqh[64 * 72];
    __shared__ __half sql[64 * 72];
    __shared__ __half skvh[64 * 72];
    __shared__ __half skvl[64 * 72];
    __shared__ float ksb[64];
    __shared__ float nrm[64];

    const int bh   = blockIdx.y;
    const int tile = blockIdx.x;
    const int b = bh >> 3, h = bh & 7;
    const size_t tok0 = (size_t)b * S_SZ + tile * 64;

    const int t    = threadIdx.x;
    const int lane = t & 31;
    const int wid  = t >> 5;
    const int wm   = wid >> 1;          // 0..3  (16-token group)
    const int wn   = wid & 1;           // 0..1  (32-col group)

    const uint32_t pqh = smem_u32(sqh), pql = smem_u32(sql);
    const uint32_t pkvh = smem_u32(skvh), pkvl = smem_u32(skvl);

    // load q hi/lo tiles: 64 rows x 8 parts(16B) each
#pragma unroll
    for (int e = 0; e < 2; e++) {
        int id   = t + e * 256;
        int row  = id >> 3;
        int part = id & 7;
        uint32_t doff = row * KVSTRIDE + part * 16;
        size_t   goff = (tok0 + row) * D_SZ + h * HD_SZ + part * 8;
        cpa16(pqh + doff, g_qh + goff);
        cpa16(pql + doff, g_ql + goff);
    }
    CPA_COMMIT();

    // convert kv fp32 -> fp16 hi/lo in smem (4096 elems, 16/thread)
    const float* kvsrc = g_kv + bh * 4096;
#pragma unroll
    for (int e = 0; e < 4; e++) {
        int i4 = t + e * 256;            // float4 index, 1024 total
        int r  = i4 >> 4;
        int c4 = (i4 & 15) << 2;
        float4 v = *(const float4*)&kvsrc[r * 64 + c4];
        __half hh[4], ll[4];
        split2h(v.x, hh[0], ll[0]); split2h(v.y, hh[1], ll[1]);
        split2h(v.z, hh[2], ll[2]); split2h(v.w, hh[3], ll[3]);
        *(uint2*)&skvh[r * 72 + c4] = *(uint2*)hh;
        *(uint2*)&skvl[r * 72 + c4] = *(uint2*)ll;
    }
    if (t < 64) ksb[t] = g_ksum[bh * HD_SZ + t];
    CPA_WAIT(0);
    __syncthreads();

    // normalizer (fp32, reconstructed q)
    if (t < 64) {
        float s = 0.f;
#pragma unroll
        for (int d = 0; d < 64; d++) {
            float qv = __half2float(sqh[t * 72 + d]) + __half2float(sql[t * 72 + d]);
            s = fmaf(qv, ksb[d], s);
        }
        nrm[t] = fmaxf(s, 1e-6f);
    }
    __syncthreads();

    // HMMA: A = q rows (non-trans), B = kv[d][m] (trans -> [m][d])
    const uint32_t aoff = (uint32_t)(wm * 16 + (lane & 15)) * KVSTRIDE
                        + ((lane >> 4) & 1) * 16;
    const uint32_t boff = ((lane & 7) + ((lane >> 3) & 1) * 8) * KVSTRIDE
                        + (wn * 32) * 2 + ((lane >> 4) & 1) * 16;

    float acc[4][4];
#pragma unroll
    for (int j = 0; j < 4; j++)
#pragma unroll
        for (int r = 0; r < 4; r++) acc[j][r] = 0.f;

#pragma unroll
    for (int ks = 0; ks < 4; ks++) {
        const uint32_t acb = ks * 32;             // A k-advance: 16 cols = 32 bytes
        const uint32_t so  = ks * 16 * KVSTRIDE;  // B k-advance: 16 d-rows
        uint32_t fqh[4], fql[4], fbh0[4], fbh1[4], fbl0[4], fbl1[4];
        LDSM4(fqh, pqh + aoff + acb);
        LDSM4(fql, pql + aoff + acb);
        LDSM4T(fbh0, pkvh + boff + so);
        LDSM4T(fbh1, pkvh + boff + so + 32);
        LDSM4T(fbl0, pkvl + boff + so);
        LDSM4T(fbl1, pkvl + boff + so + 32);
#pragma unroll
        for (int j = 0; j < 4; j++) {
            const uint32_t* bh2 = (j < 2) ? &fbh0[(j & 1) * 2] : &fbh1[(j & 1) * 2];
            const uint32_t* bl2 = (j < 2) ? &fbl0[(j & 1) * 2] : &fbl1[(j & 1) * 2];
            mma16816(acc[j], fqh, bh2);
            mma16816(acc[j], fql, bh2);
            mma16816(acc[j], fqh, bl2);
        }
    }

    // epilogue: divide by normalizer, split fp16 hi/lo, store
    const int g  = lane >> 2;
    const int tg = lane & 3;
#pragma unroll
    for (int half = 0; half < 2; half++) {
        int r = wm * 16 + g + half * 8;
        float inv = 1.0f / nrm[r];
        size_t rbase = (tok0 + r) * D_SZ + h * HD_SZ;
#pragma unroll
        for (int j = 0; j < 4; j++) {
            int col = wn * 32 + j * 8 + tg * 2;
            float v0 = acc[j][half * 2 + 0] * inv;
            float v1 = acc[j][half * 2 + 1] * inv;
            __half h0, l0, h1, l1;
            split2h(v0, h0, l0);
            split2h(v1, h1, l1);
            *(uint32_t*)&g_ah[rbase + col] = packh2(h0, h1);
            *(uint32_t*)&g_al[rbase + col] = packh2(l0, l1);
        }
    }
}

// ---------------- LayerNorm over g_y -> out (float4) --------------------------
__global__ __launch_bounds__(256)
void ln_kernel(const float* __restrict__ gamma, const float* __restrict__ beta,
               float* __restrict__ out)
{
    const int row  = blockIdx.x * 8 + (threadIdx.x >> 5);
    const int lane = threadIdx.x & 31;
    const float4* y4 = (const float4*)(g_y + (size_t)row * D_SZ);

    float4 vals[4];
    float s = 0.f, s2 = 0.f;
#pragma unroll
    for (int i = 0; i < 4; i++) {
        float4 v = y4[lane + i * 32];
        vals[i] = v;
        s += v.x + v.y + v.z + v.w;
        s2 = fmaf(v.x, v.x, s2); s2 = fmaf(v.y, v.y, s2);
        s2 = fmaf(v.z, v.z, s2); s2 = fmaf(v.w, v.w, s2);
    }
#pragma unroll
    for (int o = 16; o > 0; o >>= 1) {
        s  += __shfl_xor_sync(0xFFFFFFFFu, s, o);
        s2 += __shfl_xor_sync(0xFFFFFFFFu, s2, o);
    }
    const float mean = s * (1.0f / 512.0f);
    const float var  = s2 * (1.0f / 512.0f) - mean * mean;
    const float inv  = rsqrtf(var + 1e-5f);

    const float4* g4 = (const float4*)gamma;
    const float4* b4 = (const float4*)beta;
    float4* o4 = (float4*)(out + (size_t)row * D_SZ);
#pragma unroll
    for (int i = 0; i < 4; i++) {
        int c = lane + i * 32;
        float4 g = g4[c], bb = b4[c], v = vals[i];
        float4 r;
        r.x = (v.x - mean) * inv * g.x + bb.x;
        r.y = (v.y - mean) * inv * g.y + bb.y;
        r.z = (v.z - mean) * inv * g.z + bb.z;
        r.w = (v.w - mean) * inv * g.w + bb.w;
        o4[c] = r;
    }
}

// ---------------- launch ------------------------------------------------------
extern "C" void kernel_launch(void* const* d_in, const int* in_sizes, int n_in,
                              void* d_out, int out_size)
{
    const float* x     = (const float*)d_in[0];
    const float* Wq    = (const float*)d_in[1];
    const float* bq    = (const float*)d_in[2];
    const float* Wk    = (const float*)d_in[3];
    const float* bk    = (const float*)d_in[4];
    const float* Wv    = (const float*)d_in[5];
    const float* bv    = (const float*)d_in[6];
    const float* Wo    = (const float*)d_in[7];
    const float* bo    = (const float*)d_in[8];
    const float* gamma = (const float*)d_in[9];
    const float* beta  = (const float*)d_in[10];
    float* out = (float*)d_out;

    __half *pxh, *pxl, *pwt, *pah, *pal;
    float *py;
    cudaGetSymbolAddress((void**)&pxh, g_xh);
    cudaGetSymbolAddress((void**)&pxl, g_xl);
    cudaGetSymbolAddress((void**)&pwt, g_wt);
    cudaGetSymbolAddress((void**)&pah, g_ah);
    cudaGetSymbolAddress((void**)&pal, g_al);
    cudaGetSymbolAddress((void**)&py,  g_y);

    const int SMEM_DYN = NSTAGE * STAGE_BYTES;   // 61440
    cudaFuncSetAttribute(gemm_tc<0>, cudaFuncAttributeMaxDynamicSharedMemorySize, SMEM_DYN);
    cudaFuncSetAttribute(gemm_tc<2>, cudaFuncAttributeMaxDynamicSharedMemorySize, SMEM_DYN);

    // split input into fp16 hi/lo (+ zero kv/ksum accumulators), weights to fp16
    convert_x_kernel<<<(N_TOK * D_SZ / 4) / 256, 256>>>(x);
    convert_w_kernel<<<dim3(16, 16, 4), dim3(32, 32)>>>(Wq, Wk, Wv, Wo);

    // fused QKV projection: N_total = 1536 over [Wq|Wk|Wv]
    dim3 gqkv(3 * D_SZ / 128, N_TOK / 128);   // (12, 256)
    gemm_tc<0><<<gqkv, 256, SMEM_DYN>>>(pxh, pxl, pwt,
                                        bq, bk, bv, nullptr, nullptr);

    // kv summary + k_sum (tensor cores)
    kv_kernel<<<dim3(S_SZ / 256, BH_SZ), 256>>>();

    // normalized attention output (tensor cores, emits fp16 hi/lo)
    attn_kernel<<<dim3(S_SZ / 64, BH_SZ), 256>>>();

    // output projection + residual
    dim3 gwo(D_SZ / 128, N_TOK / 128);        // (4, 256)
    gemm_tc<2><<<gwo, 256, SMEM_DYN>>>(pah, pal, pwt + 3 * D_SZ * D_SZ,
                                       bo, nullptr, nullptr, x, py);

    // layernorm
    ln_kernel<<<N_TOK / 8, 256>>>(gamma, beta, out);
}

// round 12
// speedup vs baseline: 1.0225x; 1.0225x over previous
#include <cuda_runtime.h>
#include <cuda_fp16.h>
#include <cstdint>
#include <math.h>

// Problem constants
#define B_SZ   4
#define S_SZ   8192
#define D_SZ   512
#define H_SZ   8
#define HD_SZ  64
#define N_TOK  (B_SZ * S_SZ)          // 32768
#define BH_SZ  (B_SZ * H_SZ)          // 32

// ---------------- scratch (static __device__, no allocations) ----------------
__device__ __half g_xh[(size_t)N_TOK * D_SZ];
__device__ __half g_xl[(size_t)N_TOK * D_SZ];
__device__ __half g_wt[4 * D_SZ * D_SZ];          // transposed weights, fp16
__device__ __half g_qh[(size_t)N_TOK * D_SZ];     // feature-mapped q, hi/lo
__device__ __half g_ql[(size_t)N_TOK * D_SZ];
__device__ __half g_kh[(size_t)N_TOK * D_SZ];     // feature-mapped k, hi/lo
__device__ __half g_kl[(size_t)N_TOK * D_SZ];
__device__ __half g_vh[(size_t)N_TOK * D_SZ];     // v, hi/lo
__device__ __half g_vl[(size_t)N_TOK * D_SZ];
__device__ __half g_ah[(size_t)N_TOK * D_SZ];
__device__ __half g_al[(size_t)N_TOK * D_SZ];
__device__ float  g_y[(size_t)N_TOK * D_SZ];
__device__ float  g_kv[BH_SZ * HD_SZ * HD_SZ];
__device__ float  g_ksum[BH_SZ * HD_SZ];

// ======================= helpers ==============================================
__device__ __forceinline__ uint32_t smem_u32(const void* p) {
    uint32_t a;
    asm("{ .reg .u64 t; cvta.to.shared.u64 t, %1; cvt.u32.u64 %0, t; }"
        : "=r"(a) : "l"(p));
    return a;
}
__device__ __forceinline__ void cpa16(uint32_t dst, const void* src) {
    asm volatile("cp.async.cg.shared.global [%0], [%1], 16;" :: "r"(dst), "l"(src));
}
#define CPA_COMMIT() asm volatile("cp.async.commit_group;" ::: "memory")
#define CPA_WAIT(n)  asm volatile("cp.async.wait_group %0;" :: "n"(n) : "memory")

#define LDSM4(r, addr)                                                          \
    asm volatile("ldmatrix.sync.aligned.m8n8.x4.shared.b16 {%0,%1,%2,%3}, [%4];"\
                 : "=r"((r)[0]), "=r"((r)[1]), "=r"((r)[2]), "=r"((r)[3])       \
                 : "r"(addr))
#define LDSM4T(r, addr)                                                         \
    asm volatile("ldmatrix.sync.aligned.m8n8.x4.trans.shared.b16 {%0,%1,%2,%3}, [%4];"\
                 : "=r"((r)[0]), "=r"((r)[1]), "=r"((r)[2]), "=r"((r)[3])       \
                 : "r"(addr))

// HMMA: D(16x8,f32) += A(16x16,f16,row) * B(16x8,f16,col)
__device__ __forceinline__ void mma16816(float* d, const uint32_t* a, const uint32_t* b) {
    asm volatile(
        "mma.sync.aligned.m16n8k16.row.col.f32.f16.f16.f32 "
        "{%0,%1,%2,%3}, {%4,%5,%6,%7}, {%8,%9}, {%0,%1,%2,%3};"
        : "+f"(d[0]), "+f"(d[1]), "+f"(d[2]), "+f"(d[3])
        : "r"(a[0]), "r"(a[1]), "r"(a[2]), "r"(a[3]), "r"(b[0]), "r"(b[1]));
}

__device__ __forceinline__ void split2h(float v, __half& h, __half& l) {
    h = __float2half(v);
    l = __float2half(v - __half2float(h));
}
__device__ __forceinline__ uint32_t packh2(__half a, __half b) {
    __half2 p = __halves2half2(a, b);
    return *(uint32_t*)&p;
}

// ======================= conversion kernels ===================================
// also zeroes the kv/ksum accumulators (merged zero_acc)
__global__ __launch_bounds__(256) void convert_x_kernel(const float* __restrict__ x)
{
    size_t i = (size_t)blockIdx.x * 256 + threadIdx.x;   // float4 index
    float4 v = ((const float4*)x)[i];
    __half h[4], l[4];
    split2h(v.x, h[0], l[0]); split2h(v.y, h[1], l[1]);
    split2h(v.z, h[2], l[2]); split2h(v.w, h[3], l[3]);
    *(uint2*)&g_xh[4 * i] = *(uint2*)h;
    *(uint2*)&g_xl[4 * i] = *(uint2*)l;
    if (i < BH_SZ * HD_SZ * HD_SZ) g_kv[i] = 0.f;
    if (i < BH_SZ * HD_SZ)         g_ksum[i] = 0.f;
}

// transpose 4 weights to fp16: Wt[w][n][k] = W_w[k][n]
__global__ void convert_w_kernel(const float* __restrict__ Wq, const float* __restrict__ Wk,
                                 const float* __restrict__ Wv, const float* __restrict__ Wo)
{
    __shared__ float tile[32][33];
    const int w = blockIdx.z;
    const float* W = (w == 0) ? Wq : (w == 1) ? Wk : (w == 2) ? Wv : Wo;
    int tx = threadIdx.x, ty = threadIdx.y;
    int k = blockIdx.y * 32 + ty;
    int n = blockIdx.x * 32 + tx;
    tile[ty][tx] = W[k * D_SZ + n];
    __syncthreads();
    int nn = blockIdx.x * 32 + ty;
    int kk = blockIdx.y * 32 + tx;
    float v = tile[tx][ty];
    size_t idx = (size_t)w * D_SZ * D_SZ + (size_t)nn * D_SZ + kk;
    g_wt[idx] = __float2half(v);
}

// ======================= tensor-core GEMM (mma.sync fp16, A-split) ============
// CTA tile 128x128, BK=32, 256 threads (8 warps, 4x2), warp tile 32x64.
// 3-stage cp.async pipeline, ONE barrier per chunk, load-before-compute.
// MODE 0: fused QKV; q,k -> fp16 hi/lo (featmap), v -> fp16 hi/lo
// MODE 2: Wo (+bias, +resid) -> fp32
#define BKC     32
#define RSTRIDE 80           // bytes per smem row (32 fp16 + 16 pad)
#define A_BYTES (128 * RSTRIDE)
#define B_BYTES (128 * RSTRIDE)
#define AH_OFF  0
#define AL_OFF  (A_BYTES)
#define BH_OFF  (2 * A_BYTES)
#define STAGE_BYTES (2 * A_BYTES + B_BYTES)       // 30720
#define NSTAGE  3
#define NCHUNK  (D_SZ / BKC)                      // 16

template <int MODE>
__global__ __launch_bounds__(256, 2)
void gemm_tc(const __half* __restrict__ Ah, const __half* __restrict__ Al,
             const __half* __restrict__ Bh,
             const float* __restrict__ b0p, const float* __restrict__ b1p,
             const float* __restrict__ b2p, const float* __restrict__ resid,
             float* __restrict__ C0)
{
    extern __shared__ __align__(16) char dsm[];
    const uint32_t sb = smem_u32(dsm);

    const int t    = threadIdx.x;
    const int lane = t & 31;
    const int wid  = t >> 5;
    const int wm   = wid >> 1;          // 0..3  (32-row group)
    const int wn   = wid & 1;           // 0..1  (64-col group)
    const int m0   = blockIdx.y * 128;
    const int n0   = blockIdx.x * 128;

    float acc[2][8][4];
#pragma unroll
    for (int i = 0; i < 2; i++)
#pragma unroll
        for (int j = 0; j < 8; j++)
#pragma unroll
            for (int r = 0; r < 4; r++) acc[i][j][r] = 0.f;

    const uint32_t aoff = (uint32_t)(wm * 32 + (lane & 15)) * RSTRIDE
                        + ((lane >> 4) & 1) * 16;
    const uint32_t boff = (uint32_t)(wn * 64 + (lane & 7) + ((lane >> 4) & 1) * 8) * RSTRIDE
                        + ((lane >> 3) & 1) * 16;

    auto load_chunk = [&](int kc, int stage) {
        const uint32_t base = sb + stage * STAGE_BYTES;
        const size_t gkoff = (size_t)kc * BKC;
#pragma unroll
        for (int e = 0; e < 2; e++) {            // A: 128 rows x 4 parts = 512
            int id   = t + e * 256;
            int row  = id >> 2;
            int part = id & 3;
            uint32_t doff = row * RSTRIDE + part * 16;
            size_t   goff = (size_t)(m0 + row) * D_SZ + gkoff + part * 8;
            cpa16(base + AH_OFF + doff, Ah + goff);
            cpa16(base + AL_OFF + doff, Al + goff);
        }
#pragma unroll
        for (int e = 0; e < 2; e++) {            // B: 128 rows x 4 parts = 512
            int id   = t + e * 256;
            int row  = id >> 2;
            int part = id & 3;
            uint32_t doff = row * RSTRIDE + part * 16;
            size_t   goff = (size_t)(n0 + row) * D_SZ + gkoff + part * 8;
            cpa16(base + BH_OFF + doff, Bh + goff);
        }
        CPA_COMMIT();
    };

    auto compute_chunk = [&](int stage) {
        const uint32_t base = sb + stage * STAGE_BYTES;
        const uint32_t aH = base + AH_OFF + aoff;
        const uint32_t aL = base + AL_OFF + aoff;
        const uint32_t bH = base + BH_OFF + boff;
#pragma unroll
        for (int kk = 0; kk < 2; kk++) {
            const int cb = kk * 32;
            uint32_t fah[2][4], fal[2][4];
            LDSM4(fah[0], aH + cb);
            LDSM4(fah[1], aH + 16 * RSTRIDE + cb);
            LDSM4(fal[0], aL + cb);
            LDSM4(fal[1], aL + 16 * RSTRIDE + cb);
#pragma unroll
            for (int nh = 0; nh < 2; nh++) {
                const uint32_t bo2 = nh * 32 * RSTRIDE + cb;
                uint32_t fbh[2][4];
                LDSM4(fbh[0], bH + bo2);
                LDSM4(fbh[1], bH + bo2 + 16 * RSTRIDE);
#pragma unroll
                for (int mi = 0; mi < 2; mi++)
#pragma unroll
                    for (int nj = 0; nj < 4; nj++)
                        mma16816(acc[mi][nh * 4 + nj], fah[mi], &fbh[nj >> 1][(nj & 1) * 2]);
#pragma unroll
                for (int mi = 0; mi < 2; mi++)
#pragma unroll
                    for (int nj = 0; nj < 4; nj++)
                        mma16816(acc[mi][nh * 4 + nj], fal[mi], &fbh[nj >> 1][(nj & 1) * 2]);
            }
        }
    };

    // ---- 3-stage pipeline: one barrier per chunk, load ahead of compute ----
    load_chunk(0, 0);
    load_chunk(1, 1);
    for (int c = 0; c < NCHUNK; c++) {
        if (c + 1 < NCHUNK) { CPA_WAIT(1); } else { CPA_WAIT(0); }
        __syncthreads();
        if (c + 2 < NCHUNK) load_chunk(c + 2, (c + 2) % NSTAGE);
        compute_chunk(c % NSTAGE);
    }

    // ---- epilogue ----
    const int wsel = (MODE == 0) ? (n0 >> 9) : 0;
    const float* bias = (MODE == 0) ? ((wsel == 0) ? b0p : (wsel == 1) ? b1p : b2p) : b0p;
    const int ncol0 = (MODE == 0) ? (n0 & 511) : n0;

    const int g  = lane >> 2;
    const int tg = lane & 3;
#pragma unroll
    for (int mi = 0; mi < 2; mi++) {
#pragma unroll
        for (int half = 0; half < 2; half++) {
            int row = m0 + wm * 32 + mi * 16 + g + half * 8;
            const float* Rrow = (MODE == 2) ? (resid + (size_t)row * D_SZ) : nullptr;
#pragma unroll
            for (int nj = 0; nj < 8; nj++) {
                int col = ncol0 + wn * 64 + nj * 8 + tg * 2;
                float v0 = acc[mi][nj][half * 2 + 0] + bias[col];
                float v1 = acc[mi][nj][half * 2 + 1] + bias[col + 1];
                if (MODE == 0) {
                    if (wsel < 2) {   // feature map for q and k
                        v0 = (v0 > 0.f) ? (v0 + 1.f) : __expf(v0);
                        v1 = (v1 > 0.f) ? (v1 + 1.f) : __expf(v1);
                    }
                    size_t idx = (size_t)row * D_SZ + col;
                    __half h0, l0, h1, l1;
                    split2h(v0, h0, l0);
                    split2h(v1, h1, l1);
                    uint32_t hw = packh2(h0, h1), lw = packh2(l0, l1);
                    if (wsel == 0) {
                        *(uint32_t*)&g_qh[idx] = hw;
                        *(uint32_t*)&g_ql[idx] = lw;
                    } else if (wsel == 1) {
                        *(uint32_t*)&g_kh[idx] = hw;
                        *(uint32_t*)&g_kl[idx] = lw;
                    } else {
                        *(uint32_t*)&g_vh[idx] = hw;
                        *(uint32_t*)&g_vl[idx] = lw;
                    }
                } else {
                    v0 += Rrow[col];
                    v1 += Rrow[col + 1];
                    *(float2*)&C0[(size_t)row * D_SZ + col] = make_float2(v0, v1);
                }
            }
        }
    }
}

// ---------------- kv = K^T V per (b,h) via HMMA, plus k_sum --------------------
#define KVSTRIDE 144                       // bytes per smem row (64 fp16 + 8 pad)
__global__ __launch_bounds__(256)
void kv_kernel()
{
    __shared__ __half skh[64 * 72];
    __shared__ __half skl[64 * 72];
    __shared__ __half svh[64 * 72];
    __shared__ __half svl[64 * 72];

    const int bh    = blockIdx.y;
    const int chunk = blockIdx.x;          // 256-row chunk
    const int b = bh >> 3, h = bh & 7;
    const size_t tok0 = (size_t)b * S_SZ + chunk * 256;

    const int t    = threadIdx.x;
    const int lane = t & 31;
    const int wid  = t >> 5;
    const int d0   = (wid >> 1) * 16;
    const int m0   = (wid & 1) * 32;

    const uint32_t pkh = smem_u32(skh), pkl = smem_u32(skl);
    const uint32_t pvh = smem_u32(svh), pvl = smem_u32(svl);

    const uint32_t aoff = ((lane & 7) + ((lane >> 4) & 1) * 8) * KVSTRIDE
                        + d0 * 2 + ((lane >> 3) & 1) * 16;
    const uint32_t boff = ((lane & 7) + ((lane >> 3) & 1) * 8) * KVSTRIDE
                        + m0 * 2 + ((lane >> 4) & 1) * 16;

    float acc[4][4];
#pragma unroll
    for (int j = 0; j < 4; j++)
#pragma unroll
        for (int r = 0; r < 4; r++) acc[j][r] = 0.f;
    float ksl = 0.f;
    const int kcol  = t & 63;
    const int krow0 = (t >> 6) * 16;

    for (int it = 0; it < 4; it++) {       // 4 tiles of 64 rows
#pragma unroll
        for (int e = 0; e < 2; e++) {
            int id   = t + e * 256;
            int row  = id >> 3;
            int part = id & 7;
            uint32_t doff = row * KVSTRIDE + part * 16;
            size_t   goff = (tok0 + it * 64 + row) * D_SZ + h * HD_SZ + part * 8;
            cpa16(pkh + doff, g_kh + goff);
            cpa16(pkl + doff, g_kl + goff);
            cpa16(pvh + doff, g_vh + goff);
            cpa16(pvl + doff, g_vl + goff);
        }
        CPA_COMMIT();
        CPA_WAIT(0);
        __syncthreads();

#pragma unroll
        for (int r = 0; r < 16; r++) {
            int rr = krow0 + r;
            ksl += __half2float(skh[rr * 72 + kcol]) + __half2float(skl[rr * 72 + kcol]);
        }

#pragma unroll
        for (int ks = 0; ks < 4; ks++) {
            const uint32_t so = ks * 16 * KVSTRIDE;
            uint32_t akh[4], akl[4], bvh0[4], bvh1[4], bvl0[4], bvl1[4];
            LDSM4T(akh, pkh + aoff + so);
            LDSM4T(akl, pkl + aoff + so);
            LDSM4T(bvh0, pvh + boff + so);
            LDSM4T(bvh1, pvh + boff + so + 32);
            LDSM4T(bvl0, pvl + boff + so);
            LDSM4T(bvl1, pvl + boff + so + 32);
#pragma unroll
            for (int j = 0; j < 4; j++) {
                const uint32_t* bh2 = (j < 2) ? &bvh0[(j & 1) * 2] : &bvh1[(j & 1) * 2];
                const uint32_t* bl2 = (j < 2) ? &bvl0[(j & 1) * 2] : &bvl1[(j & 1) * 2];
                mma16816(acc[j], akh, bh2);
                mma16816(acc[j], akh, bl2);
                mma16816(acc[j], akl, bh2);
            }
        }
        __syncthreads();
    }

    float* kvdst = g_kv + bh * (HD_SZ * HD_SZ);
    const int g  = lane >> 2;
    const int tg = lane & 3;
#pragma unroll
    for (int j = 0; j < 4; j++) {
        int col = m0 + j * 8 + tg * 2;
        atomicAdd(&kvdst[(d0 + g) * HD_SZ + col],         acc[j][0]);
        atomicAdd(&kvdst[(d0 + g) * HD_SZ + col + 1],     acc[j][1]);
        atomicAdd(&kvdst[(d0 + g + 8) * HD_SZ + col],     acc[j][2]);
        atomicAdd(&kvdst[(d0 + g + 8) * HD_SZ + col + 1], acc[j][3]);
    }
    atomicAdd(&g_ksum[bh * HD_SZ + kcol], ksl);
}

// ---------------- out = (q @ kv) / max(q . ksum, 1e-6) via HMMA ----------------
__global__ __launch_bounds__(256)
void attn_kernel()
{
    __shared__ __half sqh[64 * 72];
    __shared__ __half sql[64 * 72];
    __shared__ __half skvh[64 * 72];
    __shared__ __half skvl[64 * 72];
    __shared__ float ksb[64];
    __shared__ float nrm[64];

    const int bh   = blockIdx.y;
    const int tile = blockIdx.x;
    const int b = bh >> 3, h = bh & 7;
    const size_t tok0 = (size_t)b * S_SZ + tile * 64;

    const int t    = threadIdx.x;
    const int lane = t & 31;
    const int wid  = t >> 5;
    const int wm   = wid >> 1;
    const int wn   = wid & 1;

    const uint32_t pqh = smem_u32(sqh), pql = smem_u32(sql);
    const uint32_t pkvh = smem_u32(skvh), pkvl = smem_u32(skvl);

#pragma unroll
    for (int e = 0; e < 2; e++) {
        int id   = t + e * 256;
        int row  = id >> 3;
        int part = id & 7;
        uint32_t doff = row * KVSTRIDE + part * 16;
        size_t   goff = (tok0 + row) * D_SZ + h * HD_SZ + part * 8;
        cpa16(pqh + doff, g_qh + goff);
        cpa16(pql + doff, g_ql + goff);
    }
    CPA_COMMIT();

    const float* kvsrc = g_kv + bh * 4096;
#pragma unroll
    for (int e = 0; e < 4; e++) {
        int i4 = t + e * 256;
        int r  = i4 >> 4;
        int c4 = (i4 & 15) << 2;
        float4 v = *(const float4*)&kvsrc[r * 64 + c4];
        __half hh[4], ll[4];
        split2h(v.x, hh[0], ll[0]); split2h(v.y, hh[1], ll[1]);
        split2h(v.z, hh[2], ll[2]); split2h(v.w, hh[3], ll[3]);
        *(uint2*)&skvh[r * 72 + c4] = *(uint2*)hh;
        *(uint2*)&skvl[r * 72 + c4] = *(uint2*)ll;
    }
    if (t < 64) ksb[t] = g_ksum[bh * HD_SZ + t];
    CPA_WAIT(0);
    __syncthreads();

    if (t < 64) {
        float s = 0.f;
#pragma unroll
        for (int d = 0; d < 64; d++) {
            float qv = __half2float(sqh[t * 72 + d]) + __half2float(sql[t * 72 + d]);
            s = fmaf(qv, ksb[d], s);
        }
        nrm[t] = fmaxf(s, 1e-6f);
    }
    __syncthreads();

    const uint32_t aoff = (uint32_t)(wm * 16 + (lane & 15)) * KVSTRIDE
                        + ((lane >> 4) & 1) * 16;
    const uint32_t boff = ((lane & 7) + ((lane >> 3) & 1) * 8) * KVSTRIDE
                        + (wn * 32) * 2 + ((lane >> 4) & 1) * 16;

    float acc[4][4];
#pragma unroll
    for (int j = 0; j < 4; j++)
#pragma unroll
        for (int r = 0; r < 4; r++) acc[j][r] = 0.f;

#pragma unroll
    for (int ks = 0; ks < 4; ks++) {
        const uint32_t acb = ks * 32;
        const uint32_t so  = ks * 16 * KVSTRIDE;
        uint32_t fqh[4], fql[4], fbh0[4], fbh1[4], fbl0[4], fbl1[4];
        LDSM4(fqh, pqh + aoff + acb);
        LDSM4(fql, pql + aoff + acb);
        LDSM4T(fbh0, pkvh + boff + so);
        LDSM4T(fbh1, pkvh + boff + so + 32);
        LDSM4T(fbl0, pkvl + boff + so);
        LDSM4T(fbl1, pkvl + boff + so + 32);
#pragma unroll
        for (int j = 0; j < 4; j++) {
            const uint32_t* bh2 = (j < 2) ? &fbh0[(j & 1) * 2] : &fbh1[(j & 1) * 2];
            const uint32_t* bl2 = (j < 2) ? &fbl0[(j & 1) * 2] : &fbl1[(j & 1) * 2];
            mma16816(acc[j], fqh, bh2);
            mma16816(acc[j], fql, bh2);
            mma16816(acc[j], fqh, bl2);
        }
    }

    const int g  = lane >> 2;
    const int tg = lane & 3;
#pragma unroll
    for (int half = 0; half < 2; half++) {
        int r = wm * 16 + g + half * 8;
        float inv = 1.0f / nrm[r];
        size_t rbase = (tok0 + r) * D_SZ + h * HD_SZ;
#pragma unroll
        for (int j = 0; j < 4; j++) {
            int col = wn * 32 + j * 8 + tg * 2;
            float v0 = acc[j][half * 2 + 0] * inv;
            float v1 = acc[j][half * 2 + 1] * inv;
            __half h0, l0, h1, l1;
            split2h(v0, h0, l0);
            split2h(v1, h1, l1);
            *(uint32_t*)&g_ah[rbase + col] = packh2(h0, h1);
            *(uint32_t*)&g_al[rbase + col] = packh2(l0, l1);
        }
    }
}

// ---------------- LayerNorm over g_y -> out (float4) --------------------------
__global__ __launch_bounds__(256)
void ln_kernel(const float* __restrict__ gamma, const float* __restrict__ beta,
               float* __restrict__ out)
{
    const int row  = blockIdx.x * 8 + (threadIdx.x >> 5);
    const int lane = threadIdx.x & 31;
    const float4* y4 = (const float4*)(g_y + (size_t)row * D_SZ);

    float4 vals[4];
    float s = 0.f, s2 = 0.f;
#pragma unroll
    for (int i = 0; i < 4; i++) {
        float4 v = y4[lane + i * 32];
        vals[i] = v;
        s += v.x + v.y + v.z + v.w;
        s2 = fmaf(v.x, v.x, s2); s2 = fmaf(v.y, v.y, s2);
        s2 = fmaf(v.z, v.z, s2); s2 = fmaf(v.w, v.w, s2);
    }
#pragma unroll
    for (int o = 16; o > 0; o >>= 1) {
        s  += __shfl_xor_sync(0xFFFFFFFFu, s, o);
        s2 += __shfl_xor_sync(0xFFFFFFFFu, s2, o);
    }
    const float mean = s * (1.0f / 512.0f);
    const float var  = s2 * (1.0f / 512.0f) - mean * mean;
    const float inv  = rsqrtf(var + 1e-5f);

    const float4* g4 = (const float4*)gamma;
    const float4* b4 = (const float4*)beta;
    float4* o4 = (float4*)(out + (size_t)row * D_SZ);
#pragma unroll
    for (int i = 0; i < 4; i++) {
        int c = lane + i * 32;
        float4 g = g4[c], bb = b4[c], v = vals[i];
        float4 r;
        r.x = (v.x - mean) * inv * g.x + bb.x;
        r.y = (v.y - mean) * inv * g.y + bb.y;
        r.z = (v.z - mean) * inv * g.z + bb.z;
        r.w = (v.w - mean) * inv * g.w + bb.w;
        o4[c] = r;
    }
}

// ---------------- launch ------------------------------------------------------
extern "C" void kernel_launch(void* const* d_in, const int* in_sizes, int n_in,
                              void* d_out, int out_size)
{
    const float* x     = (const float*)d_in[0];
    const float* Wq    = (const float*)d_in[1];
    const float* bq    = (const float*)d_in[2];
    const float* Wk    = (const float*)d_in[3];
    const float* bk    = (const float*)d_in[4];
    const float* Wv    = (const float*)d_in[5];
    const float* bv    = (const float*)d_in[6];
    const float* Wo    = (const float*)d_in[7];
    const float* bo    = (const float*)d_in[8];
    const float* gamma = (const float*)d_in[9];
    const float* beta  = (const float*)d_in[10];
    float* out = (float*)d_out;

    __half *pxh, *pxl, *pwt, *pah, *pal;
    float *py;
    cudaGetSymbolAddress((void**)&pxh, g_xh);
    cudaGetSymbolAddress((void**)&pxl, g_xl);
    cudaGetSymbolAddress((void**)&pwt, g_wt);
    cudaGetSymbolAddress((void**)&pah, g_ah);
    cudaGetSymbolAddress((void**)&pal, g_al);
    cudaGetSymbolAddress((void**)&py,  g_y);

    const int SMEM_DYN = NSTAGE * STAGE_BYTES;   // 92160
    cudaFuncSetAttribute(gemm_tc<0>, cudaFuncAttributeMaxDynamicSharedMemorySize, SMEM_DYN);
    cudaFuncSetAttribute(gemm_tc<2>, cudaFuncAttributeMaxDynamicSharedMemorySize, SMEM_DYN);

    // split input into fp16 hi/lo (+ zero kv/ksum accumulators), weights to fp16
    convert_x_kernel<<<(N_TOK * D_SZ / 4) / 256, 256>>>(x);
    convert_w_kernel<<<dim3(16, 16, 4), dim3(32, 32)>>>(Wq, Wk, Wv, Wo);

    // fused QKV projection: N_total = 1536 over [Wq|Wk|Wv]
    dim3 gqkv(3 * D_SZ / 128, N_TOK / 128);   // (12, 256)
    gemm_tc<0><<<gqkv, 256, SMEM_DYN>>>(pxh, pxl, pwt,
                                        bq, bk, bv, nullptr, nullptr);

    // kv summary + k_sum (tensor cores)
    kv_kernel<<<dim3(S_SZ / 256, BH_SZ), 256>>>();

    // normalized attention output (tensor cores, emits fp16 hi/lo)
    attn_kernel<<<dim3(S_SZ / 64, BH_SZ), 256>>>();

    // output projection + residual
    dim3 gwo(D_SZ / 128, N_TOK / 128);        // (4, 256)
    gemm_tc<2><<<gwo, 256, SMEM_DYN>>>(pah, pal, pwt + 3 * D_SZ * D_SZ,
                                       bo, nullptr, nullptr, x, py);

    // layernorm
    ln_kernel<<<N_TOK / 8, 256>>>(gamma, beta, out);
}

// round 14
// speedup vs baseline: 1.0673x; 1.0439x over previous
#include <cuda_runtime.h>
#include <cuda_fp16.h>
#include <cstdint>
#include <math.h>

// Problem constants
#define B_SZ   4
#define S_SZ   8192
#define D_SZ   512
#define H_SZ   8
#define HD_SZ  64
#define N_TOK  (B_SZ * S_SZ)          // 32768
#define BH_SZ  (B_SZ * H_SZ)          // 32

// ---------------- scratch (static __device__, no allocations) ----------------
__device__ __half g_xh[(size_t)N_TOK * D_SZ];
__device__ __half g_xl[(size_t)N_TOK * D_SZ];
__device__ __half g_wt[4 * D_SZ * D_SZ];          // transposed weights, fp16
__device__ __half g_qh[(size_t)N_TOK * D_SZ];     // feature-mapped q, hi/lo
__device__ __half g_ql[(size_t)N_TOK * D_SZ];
__device__ __half g_kh[(size_t)N_TOK * D_SZ];     // feature-mapped k, hi/lo
__device__ __half g_kl[(size_t)N_TOK * D_SZ];
__device__ __half g_vh[(size_t)N_TOK * D_SZ];     // v, hi/lo
__device__ __half g_vl[(size_t)N_TOK * D_SZ];
__device__ __half g_ah[(size_t)N_TOK * D_SZ];
__device__ __half g_al[(size_t)N_TOK * D_SZ];
__device__ float  g_y[(size_t)N_TOK * D_SZ];
__device__ float  g_kv[BH_SZ * HD_SZ * HD_SZ];
__device__ float  g_ksum[BH_SZ * HD_SZ];

// ======================= helpers ==============================================
__device__ __forceinline__ uint32_t smem_u32(const void* p) {
    uint32_t a;
    asm("{ .reg .u64 t; cvta.to.shared.u64 t, %1; cvt.u32.u64 %0, t; }"
        : "=r"(a) : "l"(p));
    return a;
}
__device__ __forceinline__ void cpa16(uint32_t dst, const void* src) {
    asm volatile("cp.async.cg.shared.global [%0], [%1], 16;" :: "r"(dst), "l"(src));
}
#define CPA_COMMIT() asm volatile("cp.async.commit_group;" ::: "memory")
#define CPA_WAIT(n)  asm volatile("cp.async.wait_group %0;" :: "n"(n) : "memory")

#define LDSM4(r, addr)                                                          \
    asm volatile("ldmatrix.sync.aligned.m8n8.x4.shared.b16 {%0,%1,%2,%3}, [%4];"\
                 : "=r"((r)[0]), "=r"((r)[1]), "=r"((r)[2]), "=r"((r)[3])       \
                 : "r"(addr))
#define LDSM4T(r, addr)                                                         \
    asm volatile("ldmatrix.sync.aligned.m8n8.x4.trans.shared.b16 {%0,%1,%2,%3}, [%4];"\
                 : "=r"((r)[0]), "=r"((r)[1]), "=r"((r)[2]), "=r"((r)[3])       \
                 : "r"(addr))

// HMMA: D(16x8,f32) += A(16x16,f16,row) * B(16x8,f16,col)
__device__ __forceinline__ void mma16816(float* d, const uint32_t* a, const uint32_t* b) {
    asm volatile(
        "mma.sync.aligned.m16n8k16.row.col.f32.f16.f16.f32 "
        "{%0,%1,%2,%3}, {%4,%5,%6,%7}, {%8,%9}, {%0,%1,%2,%3};"
        : "+f"(d[0]), "+f"(d[1]), "+f"(d[2]), "+f"(d[3])
        : "r"(a[0]), "r"(a[1]), "r"(a[2]), "r"(a[3]), "r"(b[0]), "r"(b[1]));
}

__device__ __forceinline__ void split2h(float v, __half& h, __half& l) {
    h = __float2half(v);
    l = __float2half(v - __half2float(h));
}
__device__ __forceinline__ uint32_t packh2(__half a, __half b) {
    __half2 p = __halves2half2(a, b);
    return *(uint32_t*)&p;
}

// ======================= conversion kernels ===================================
// also zeroes the kv/ksum accumulators (merged zero_acc)
__global__ __launch_bounds__(256) void convert_x_kernel(const float* __restrict__ x)
{
    size_t i = (size_t)blockIdx.x * 256 + threadIdx.x;   // float4 index
    float4 v = ((const float4*)x)[i];
    __half h[4], l[4];
    split2h(v.x, h[0], l[0]); split2h(v.y, h[1], l[1]);
    split2h(v.z, h[2], l[2]); split2h(v.w, h[3], l[3]);
    *(uint2*)&g_xh[4 * i] = *(uint2*)h;
    *(uint2*)&g_xl[4 * i] = *(uint2*)l;
    if (i < BH_SZ * HD_SZ * HD_SZ) g_kv[i] = 0.f;
    if (i < BH_SZ * HD_SZ)         g_ksum[i] = 0.f;
}

// transpose 4 weights to fp16: Wt[w][n][k] = W_w[k][n]
__global__ void convert_w_kernel(const float* __restrict__ Wq, const float* __restrict__ Wk,
                                 const float* __restrict__ Wv, const float* __restrict__ Wo)
{
    __shared__ float tile[32][33];
    const int w = blockIdx.z;
    const float* W = (w == 0) ? Wq : (w == 1) ? Wk : (w == 2) ? Wv : Wo;
    int tx = threadIdx.x, ty = threadIdx.y;
    int k = blockIdx.y * 32 + ty;
    int n = blockIdx.x * 32 + tx;
    tile[ty][tx] = W[k * D_SZ + n];
    __syncthreads();
    int nn = blockIdx.x * 32 + ty;
    int kk = blockIdx.y * 32 + tx;
    float v = tile[tx][ty];
    size_t idx = (size_t)w * D_SZ * D_SZ + (size_t)nn * D_SZ + kk;
    g_wt[idx] = __float2half(v);
}

// ======================= tensor-core GEMM (mma.sync fp16, A-split) ============
// CTA tile 128x128, BK=64, 256 threads (8 warps, 4x2), warp tile 32x64.
// 2-stage cp.async pipeline, R5-proven ordering (load -> wait -> sync -> compute -> sync).
// MODE 0: fused QKV; q,k -> fp16 hi/lo (featmap), v -> fp16 hi/lo
// MODE 2: Wo (+bias, +resid) -> fp32
#define BKC     64
#define RSTRIDE 144          // bytes per smem row (64 fp16 + 16 pad)
#define A_BYTES (128 * RSTRIDE)
#define B_BYTES (128 * RSTRIDE)
#define AH_OFF  0
#define AL_OFF  (A_BYTES)
#define BH_OFF  (2 * A_BYTES)
#define STAGE_BYTES (2 * A_BYTES + B_BYTES)       // 55296
#define NSTAGE  2
#define NCHUNK  (D_SZ / BKC)                      // 8

template <int MODE>
__global__ __launch_bounds__(256, 2)
void gemm_tc(const __half* __restrict__ Ah, const __half* __restrict__ Al,
             const __half* __restrict__ Bh,
             const float* __restrict__ b0p, const float* __restrict__ b1p,
             const float* __restrict__ b2p, const float* __restrict__ resid,
             float* __restrict__ C0)
{
    extern __shared__ __align__(16) char dsm[];
    const uint32_t sb = smem_u32(dsm);

    const int t    = threadIdx.x;
    const int lane = t & 31;
    const int wid  = t >> 5;
    const int wm   = wid >> 1;          // 0..3  (32-row group)
    const int wn   = wid & 1;           // 0..1  (64-col group)
    const int m0   = blockIdx.y * 128;
    const int n0   = blockIdx.x * 128;

    float acc[2][8][4];
#pragma unroll
    for (int i = 0; i < 2; i++)
#pragma unroll
        for (int j = 0; j < 8; j++)
#pragma unroll
            for (int r = 0; r < 4; r++) acc[i][j][r] = 0.f;

    const uint32_t aoff = (uint32_t)(wm * 32 + (lane & 15)) * RSTRIDE
                        + ((lane >> 4) & 1) * 16;
    const uint32_t boff = (uint32_t)(wn * 64 + (lane & 7) + ((lane >> 4) & 1) * 8) * RSTRIDE
                        + ((lane >> 3) & 1) * 16;

    // ---- async tile loader (BK=64: 128B per row, 8 x 16B parts) ----
    auto load_chunk = [&](int kc, int stage) {
        const uint32_t base = sb + stage * STAGE_BYTES;
        const size_t gkoff = (size_t)kc * BKC;
#pragma unroll
        for (int e = 0; e < 4; e++) {            // A: 128 rows x 8 parts = 1024
            int id   = t + e * 256;
            int row  = id >> 3;
            int part = id & 7;
            uint32_t doff = row * RSTRIDE + part * 16;
            size_t   goff = (size_t)(m0 + row) * D_SZ + gkoff + part * 8;
            cpa16(base + AH_OFF + doff, Ah + goff);
            cpa16(base + AL_OFF + doff, Al + goff);
        }
#pragma unroll
        for (int e = 0; e < 4; e++) {            // B: 128 rows x 8 parts = 1024
            int id   = t + e * 256;
            int row  = id >> 3;
            int part = id & 7;
            uint32_t doff = row * RSTRIDE + part * 16;
            size_t   goff = (size_t)(n0 + row) * D_SZ + gkoff + part * 8;
            cpa16(base + BH_OFF + doff, Bh + goff);
        }
        CPA_COMMIT();
    };

    // ---- compute one BK=64 chunk (4 kk steps x 2 n-halves) ----
    auto compute_chunk = [&](int stage) {
        const uint32_t base = sb + stage * STAGE_BYTES;
        const uint32_t aH = base + AH_OFF + aoff;
        const uint32_t aL = base + AL_OFF + aoff;
        const uint32_t bH = base + BH_OFF + boff;
#pragma unroll
        for (int kk = 0; kk < 4; kk++) {
            const int cb = kk * 32;
            uint32_t fah[2][4], fal[2][4];
            LDSM4(fah[0], aH + cb);
            LDSM4(fah[1], aH + 16 * RSTRIDE + cb);
            LDSM4(fal[0], aL + cb);
            LDSM4(fal[1], aL + 16 * RSTRIDE + cb);
#pragma unroll
            for (int nh = 0; nh < 2; nh++) {
                const uint32_t bo2 = nh * 32 * RSTRIDE + cb;
                uint32_t fbh[2][4];
                LDSM4(fbh[0], bH + bo2);
                LDSM4(fbh[1], bH + bo2 + 16 * RSTRIDE);
#pragma unroll
                for (int mi = 0; mi < 2; mi++)
#pragma unroll
                    for (int nj = 0; nj < 4; nj++)
                        mma16816(acc[mi][nh * 4 + nj], fah[mi], &fbh[nj >> 1][(nj & 1) * 2]);
#pragma unroll
                for (int mi = 0; mi < 2; mi++)
#pragma unroll
                    for (int nj = 0; nj < 4; nj++)
                        mma16816(acc[mi][nh * 4 + nj], fal[mi], &fbh[nj >> 1][(nj & 1) * 2]);
            }
        }
    };

    // ---- 2-stage pipeline, R5-proven ordering ----
    load_chunk(0, 0);
    for (int c = 0; c < NCHUNK; c++) {
        if (c + 1 < NCHUNK) {
            load_chunk(c + 1, (c + 1) & 1);
            CPA_WAIT(1);
        } else {
            CPA_WAIT(0);
        }
        __syncthreads();
        compute_chunk(c & 1);
        __syncthreads();
    }

    // ---- epilogue ----
    const int wsel = (MODE == 0) ? (n0 >> 9) : 0;
    const float* bias = (MODE == 0) ? ((wsel == 0) ? b0p : (wsel == 1) ? b1p : b2p) : b0p;
    const int ncol0 = (MODE == 0) ? (n0 & 511) : n0;

    const int g  = lane >> 2;
    const int tg = lane & 3;
#pragma unroll
    for (int mi = 0; mi < 2; mi++) {
#pragma unroll
        for (int half = 0; half < 2; half++) {
            int row = m0 + wm * 32 + mi * 16 + g + half * 8;
            const float* Rrow = (MODE == 2) ? (resid + (size_t)row * D_SZ) : nullptr;
#pragma unroll
            for (int nj = 0; nj < 8; nj++) {
                int col = ncol0 + wn * 64 + nj * 8 + tg * 2;
                float v0 = acc[mi][nj][half * 2 + 0] + bias[col];
                float v1 = acc[mi][nj][half * 2 + 1] + bias[col + 1];
                if (MODE == 0) {
                    if (wsel < 2) {   // feature map for q and k
                        v0 = (v0 > 0.f) ? (v0 + 1.f) : __expf(v0);
                        v1 = (v1 > 0.f) ? (v1 + 1.f) : __expf(v1);
                    }
                    size_t idx = (size_t)row * D_SZ + col;
                    __half h0, l0, h1, l1;
                    split2h(v0, h0, l0);
                    split2h(v1, h1, l1);
                    uint32_t hw = packh2(h0, h1), lw = packh2(l0, l1);
                    if (wsel == 0) {
                        *(uint32_t*)&g_qh[idx] = hw;
                        *(uint32_t*)&g_ql[idx] = lw;
                    } else if (wsel == 1) {
                        *(uint32_t*)&g_kh[idx] = hw;
                        *(uint32_t*)&g_kl[idx] = lw;
                    } else {
                        *(uint32_t*)&g_vh[idx] = hw;
                        *(uint32_t*)&g_vl[idx] = lw;
                    }
                } else {
                    v0 += Rrow[col];
                    v1 += Rrow[col + 1];
                    *(float2*)&C0[(size_t)row * D_SZ + col] = make_float2(v0, v1);
                }
            }
        }
    }
}

// ---------------- kv = K^T V per (b,h) via HMMA, plus k_sum --------------------
#define KVSTRIDE 144                       // bytes per smem row (64 fp16 + 8 pad)
__global__ __launch_bounds__(256)
void kv_kernel()
{
    __shared__ __half skh[64 * 72];
    __shared__ __half skl[64 * 72];
    __shared__ __half svh[64 * 72];
    __shared__ __half svl[64 * 72];

    const int bh    = blockIdx.y;
    const int chunk = blockIdx.x;          // 256-row chunk
    const int b = bh >> 3, h = bh & 7;
    const size_t tok0 = (size_t)b * S_SZ + chunk * 256;

    const int t    = threadIdx.x;
    const int lane = t & 31;
    const int wid  = t >> 5;
    const int d0   = (wid >> 1) * 16;
    const int m0   = (wid & 1) * 32;

    const uint32_t pkh = smem_u32(skh), pkl = smem_u32(skl);
    const uint32_t pvh = smem_u32(svh), pvl = smem_u32(svl);

    const uint32_t aoff = ((lane & 7) + ((lane >> 4) & 1) * 8) * KVSTRIDE
                        + d0 * 2 + ((lane >> 3) & 1) * 16;
    const uint32_t boff = ((lane & 7) + ((lane >> 3) & 1) * 8) * KVSTRIDE
                        + m0 * 2 + ((lane >> 4) & 1) * 16;

    float acc[4][4];
#pragma unroll
    for (int j = 0; j < 4; j++)
#pragma unroll
        for (int r = 0; r < 4; r++) acc[j][r] = 0.f;
    float ksl = 0.f;
    const int kcol  = t & 63;
    const int krow0 = (t >> 6) * 16;

    for (int it = 0; it < 4; it++) {       // 4 tiles of 64 rows
#pragma unroll
        for (int e = 0; e < 2; e++) {
            int id   = t + e * 256;
            int row  = id >> 3;
            int part = id & 7;
            uint32_t doff = row * KVSTRIDE + part * 16;
            size_t   goff = (tok0 + it * 64 + row) * D_SZ + h * HD_SZ + part * 8;
            cpa16(pkh + doff, g_kh + goff);
            cpa16(pkl + doff, g_kl + goff);
            cpa16(pvh + doff, g_vh + goff);
            cpa16(pvl + doff, g_vl + goff);
        }
        CPA_COMMIT();
        CPA_WAIT(0);
        __syncthreads();

#pragma unroll
        for (int r = 0; r < 16; r++) {
            int rr = krow0 + r;
            ksl += __half2float(skh[rr * 72 + kcol]) + __half2float(skl[rr * 72 + kcol]);
        }

#pragma unroll
        for (int ks = 0; ks < 4; ks++) {
            const uint32_t so = ks * 16 * KVSTRIDE;
            uint32_t akh[4], akl[4], bvh0[4], bvh1[4], bvl0[4], bvl1[4];
            LDSM4T(akh, pkh + aoff + so);
            LDSM4T(akl, pkl + aoff + so);
            LDSM4T(bvh0, pvh + boff + so);
            LDSM4T(bvh1, pvh + boff + so + 32);
            LDSM4T(bvl0, pvl + boff + so);
            LDSM4T(bvl1, pvl + boff + so + 32);
#pragma unroll
            for (int j = 0; j < 4; j++) {
                const uint32_t* bh2 = (j < 2) ? &bvh0[(j & 1) * 2] : &bvh1[(j & 1) * 2];
                const uint32_t* bl2 = (j < 2) ? &bvl0[(j & 1) * 2] : &bvl1[(j & 1) * 2];
                mma16816(acc[j], akh, bh2);
                mma16816(acc[j], akh, bl2);
                mma16816(acc[j], akl, bh2);
            }
        }
        __syncthreads();
    }

    float* kvdst = g_kv + bh * (HD_SZ * HD_SZ);
    const int g  = lane >> 2;
    const int tg = lane & 3;
#pragma unroll
    for (int j = 0; j < 4; j++) {
        int col = m0 + j * 8 + tg * 2;
        atomicAdd(&kvdst[(d0 + g) * HD_SZ + col],         acc[j][0]);
        atomicAdd(&kvdst[(d0 + g) * HD_SZ + col + 1],     acc[j][1]);
        atomicAdd(&kvdst[(d0 + g + 8) * HD_SZ + col],     acc[j][2]);
        atomicAdd(&kvdst[(d0 + g + 8) * HD_SZ + col + 1], acc[j][3]);
    }
    atomicAdd(&g_ksum[bh * HD_SZ + kcol], ksl);
}

// ---------------- out = (q @ kv) / max(q . ksum, 1e-6) via HMMA ----------------
__global__ __launch_bounds__(256)
void attn_kernel()
{
    __shared__ __half sqh[64 * 72];
    __shared__ __half sql[64 * 72];
    __shared__ __half skvh[64 * 72];
    __shared__ __half skvl[64 * 72];
    __shared__ float ksb[64];
    __shared__ float nrm[64];

    const int bh   = blockIdx.y;
    const int tile = blockIdx.x;
    const int b = bh >> 3, h = bh & 7;
    const size_t tok0 = (size_t)b * S_SZ + tile * 64;

    const int t    = threadIdx.x;
    const int lane = t & 31;
    const int wid  = t >> 5;
    const int wm   = wid >> 1;
    const int wn   = wid & 1;

    const uint32_t pqh = smem_u32(sqh), pql = smem_u32(sql);
    const uint32_t pkvh = smem_u32(skvh), pkvl = smem_u32(skvl);

#pragma unroll
    for (int e = 0; e < 2; e++) {
        int id   = t + e * 256;
        int row  = id >> 3;
        int part = id & 7;
        uint32_t doff = row * KVSTRIDE + part * 16;
        size_t   goff = (tok0 + row) * D_SZ + h * HD_SZ + part * 8;
        cpa16(pqh + doff, g_qh + goff);
        cpa16(pql + doff, g_ql + goff);
    }
    CPA_COMMIT();

    const float* kvsrc = g_kv + bh * 4096;
#pragma unroll
    for (int e = 0; e < 4; e++) {
        int i4 = t + e * 256;
        int r  = i4 >> 4;
        int c4 = (i4 & 15) << 2;
        float4 v = *(const float4*)&kvsrc[r * 64 + c4];
        __half hh[4], ll[4];
        split2h(v.x, hh[0], ll[0]); split2h(v.y, hh[1], ll[1]);
        split2h(v.z, hh[2], ll[2]); split2h(v.w, hh[3], ll[3]);
        *(uint2*)&skvh[r * 72 + c4] = *(uint2*)hh;
        *(uint2*)&skvl[r * 72 + c4] = *(uint2*)ll;
    }
    if (t < 64) ksb[t] = g_ksum[bh * HD_SZ + t];
    CPA_WAIT(0);
    __syncthreads();

    if (t < 64) {
        float s = 0.f;
#pragma unroll
        for (int d = 0; d < 64; d++) {
            float qv = __half2float(sqh[t * 72 + d]) + __half2float(sql[t * 72 + d]);
            s = fmaf(qv, ksb[d], s);
        }
        nrm[t] = fmaxf(s, 1e-6f);
    }
    __syncthreads();

    const uint32_t aoff = (uint32_t)(wm * 16 + (lane & 15)) * KVSTRIDE
                        + ((lane >> 4) & 1) * 16;
    const uint32_t boff = ((lane & 7) + ((lane >> 3) & 1) * 8) * KVSTRIDE
                        + (wn * 32) * 2 + ((lane >> 4) & 1) * 16;

    float acc[4][4];
#pragma unroll
    for (int j = 0; j < 4; j++)
#pragma unroll
        for (int r = 0; r < 4; r++) acc[j][r] = 0.f;

#pragma unroll
    for (int ks = 0; ks < 4; ks++) {
        const uint32_t acb = ks * 32;
        const uint32_t so  = ks * 16 * KVSTRIDE;
        uint32_t fqh[4], fql[4], fbh0[4], fbh1[4], fbl0[4], fbl1[4];
        LDSM4(fqh, pqh + aoff + acb);
        LDSM4(fql, pql + aoff + acb);
        LDSM4T(fbh0, pkvh + boff + so);
        LDSM4T(fbh1, pkvh + boff + so + 32);
        LDSM4T(fbl0, pkvl + boff + so);
        LDSM4T(fbl1, pkvl + boff + so + 32);
#pragma unroll
        for (int j = 0; j < 4; j++) {
            const uint32_t* bh2 = (j < 2) ? &fbh0[(j & 1) * 2] : &fbh1[(j & 1) * 2];
            const uint32_t* bl2 = (j < 2) ? &fbl0[(j & 1) * 2] : &fbl1[(j & 1) * 2];
            mma16816(acc[j], fqh, bh2);
            mma16816(acc[j], fql, bh2);
            mma16816(acc[j], fqh, bl2);
        }
    }

    const int g  = lane >> 2;
    const int tg = lane & 3;
#pragma unroll
    for (int half = 0; half < 2; half++) {
        int r = wm * 16 + g + half * 8;
        float inv = 1.0f / nrm[r];
        size_t rbase = (tok0 + r) * D_SZ + h * HD_SZ;
#pragma unroll
        for (int j = 0; j < 4; j++) {
            int col = wn * 32 + j * 8 + tg * 2;
            float v0 = acc[j][half * 2 + 0] * inv;
            float v1 = acc[j][half * 2 + 1] * inv;
            __half h0, l0, h1, l1;
            split2h(v0, h0, l0);
            split2h(v1, h1, l1);
            *(uint32_t*)&g_ah[rbase + col] = packh2(h0, h1);
            *(uint32_t*)&g_al[rbase + col] = packh2(l0, l1);
        }
    }
}

// ---------------- LayerNorm over g_y -> out (float4) --------------------------
__global__ __launch_bounds__(256)
void ln_kernel(const float* __restrict__ gamma, const float* __restrict__ beta,
               float* __restrict__ out)
{
    const int row  = blockIdx.x * 8 + (threadIdx.x >> 5);
    const int lane = threadIdx.x & 31;
    const float4* y4 = (const float4*)(g_y + (size_t)row * D_SZ);

    float4 vals[4];
    float s = 0.f, s2 = 0.f;
#pragma unroll
    for (int i = 0; i < 4; i++) {
        float4 v = y4[lane + i * 32];
        vals[i] = v;
        s += v.x + v.y + v.z + v.w;
        s2 = fmaf(v.x, v.x, s2); s2 = fmaf(v.y, v.y, s2);
        s2 = fmaf(v.z, v.z, s2); s2 = fmaf(v.w, v.w, s2);
    }
#pragma unroll
    for (int o = 16; o > 0; o >>= 1) {
        s  += __shfl_xor_sync(0xFFFFFFFFu, s, o);
        s2 += __shfl_xor_sync(0xFFFFFFFFu, s2, o);
    }
    const float mean = s * (1.0f / 512.0f);
    const float var  = s2 * (1.0f / 512.0f) - mean * mean;
    const float inv  = rsqrtf(var + 1e-5f);

    const float4* g4 = (const float4*)gamma;
    const float4* b4 = (const float4*)beta;
    float4* o4 = (float4*)(out + (size_t)row * D_SZ);
#pragma unroll
    for (int i = 0; i < 4; i++) {
        int c = lane + i * 32;
        float4 g = g4[c], bb = b4[c], v = vals[i];
        float4 r;
        r.x = (v.x - mean) * inv * g.x + bb.x;
        r.y = (v.y - mean) * inv * g.y + bb.y;
        r.z = (v.z - mean) * inv * g.z + bb.z;
        r.w = (v.w - mean) * inv * g.w + bb.w;
        o4[c] = r;
    }
}

// ---------------- launch ------------------------------------------------------
extern "C" void kernel_launch(void* const* d_in, const int* in_sizes, int n_in,
                              void* d_out, int out_size)
{
    const float* x     = (const float*)d_in[0];
    const float* Wq    = (const float*)d_in[1];
    const float* bq    = (const float*)d_in[2];
    const float* Wk    = (const float*)d_in[3];
    const float* bk    = (const float*)d_in[4];
    const float* Wv    = (const float*)d_in[5];
    const float* bv    = (const float*)d_in[6];
    const float* Wo    = (const float*)d_in[7];
    const float* bo    = (const float*)d_in[8];
    const float* gamma = (const float*)d_in[9];
    const float* beta  = (const float*)d_in[10];
    float* out = (float*)d_out;

    __half *pxh, *pxl, *pwt, *pah, *pal;
    float *py;
    cudaGetSymbolAddress((void**)&pxh, g_xh);
    cudaGetSymbolAddress((void**)&pxl, g_xl);
    cudaGetSymbolAddress((void**)&pwt, g_wt);
    cudaGetSymbolAddress((void**)&pah, g_ah);
    cudaGetSymbolAddress((void**)&pal, g_al);
    cudaGetSymbolAddress((void**)&py,  g_y);

    const int SMEM_DYN = NSTAGE * STAGE_BYTES;   // 110592
    cudaFuncSetAttribute(gemm_tc<0>, cudaFuncAttributeMaxDynamicSharedMemorySize, SMEM_DYN);
    cudaFuncSetAttribute(gemm_tc<2>, cudaFuncAttributeMaxDynamicSharedMemorySize, SMEM_DYN);

    // split input into fp16 hi/lo (+ zero kv/ksum accumulators), weights to fp16
    convert_x_kernel<<<(N_TOK * D_SZ / 4) / 256, 256>>>(x);
    convert_w_kernel<<<dim3(16, 16, 4), dim3(32, 32)>>>(Wq, Wk, Wv, Wo);

    // fused QKV projection: N_total = 1536 over [Wq|Wk|Wv]
    dim3 gqkv(3 * D_SZ / 128, N_TOK / 128);   // (12, 256)
    gemm_tc<0><<<gqkv, 256, SMEM_DYN>>>(pxh, pxl, pwt,
                                        bq, bk, bv, nullptr, nullptr);

    // kv summary + k_sum (tensor cores)
    kv_kernel<<<dim3(S_SZ / 256, BH_SZ), 256>>>();

    // normalized attention output (tensor cores, emits fp16 hi/lo)
    attn_kernel<<<dim3(S_SZ / 64, BH_SZ), 256>>>();

    // output projection + residual
    dim3 gwo(D_SZ / 128, N_TOK / 128);        // (4, 256)
    gemm_tc<2><<<gwo, 256, SMEM_DYN>>>(pah, pal, pwt + 3 * D_SZ * D_SZ,
                                       bo, nullptr, nullptr, x, py);

    // layernorm
    ln_kernel<<<N_TOK / 8, 256>>>(gamma, beta, out);
}

// round 15
// speedup vs baseline: 1.4456x; 1.3544x over previous
#include <cuda_runtime.h>
#include <cuda_fp16.h>
#include <cstdint>
#include <math.h>

// Problem constants
#define B_SZ   4
#define S_SZ   8192
#define D_SZ   512
#define H_SZ   8
#define HD_SZ  64
#define N_TOK  (B_SZ * S_SZ)          // 32768
#define BH_SZ  (B_SZ * H_SZ)          // 32

// ---------------- scratch (static __device__, no allocations) ----------------
__device__ __half g_xh[(size_t)N_TOK * D_SZ];
__device__ __half g_wt[4 * D_SZ * D_SZ];          // transposed weights, fp16
__device__ __half g_qh[(size_t)N_TOK * D_SZ];     // feature-mapped q, hi/lo
__device__ __half g_ql[(size_t)N_TOK * D_SZ];
__device__ __half g_kh[(size_t)N_TOK * D_SZ];     // feature-mapped k, hi/lo
__device__ __half g_kl[(size_t)N_TOK * D_SZ];
__device__ __half g_vh[(size_t)N_TOK * D_SZ];     // v, hi/lo
__device__ __half g_vl[(size_t)N_TOK * D_SZ];
__device__ __half g_ah[(size_t)N_TOK * D_SZ];     // attention output, fp16
__device__ float  g_y[(size_t)N_TOK * D_SZ];
__device__ float  g_kv[BH_SZ * HD_SZ * HD_SZ];
__device__ float  g_ksum[BH_SZ * HD_SZ];

// ======================= helpers ==============================================
__device__ __forceinline__ uint32_t smem_u32(const void* p) {
    uint32_t a;
    asm("{ .reg .u64 t; cvta.to.shared.u64 t, %1; cvt.u32.u64 %0, t; }"
        : "=r"(a) : "l"(p));
    return a;
}
__device__ __forceinline__ void cpa16(uint32_t dst, const void* src) {
    asm volatile("cp.async.cg.shared.global [%0], [%1], 16;" :: "r"(dst), "l"(src));
}
#define CPA_COMMIT() asm volatile("cp.async.commit_group;" ::: "memory")
#define CPA_WAIT(n)  asm volatile("cp.async.wait_group %0;" :: "n"(n) : "memory")

#define LDSM4(r, addr)                                                          \
    asm volatile("ldmatrix.sync.aligned.m8n8.x4.shared.b16 {%0,%1,%2,%3}, [%4];"\
                 : "=r"((r)[0]), "=r"((r)[1]), "=r"((r)[2]), "=r"((r)[3])       \
                 : "r"(addr))
#define LDSM4T(r, addr)                                                         \
    asm volatile("ldmatrix.sync.aligned.m8n8.x4.trans.shared.b16 {%0,%1,%2,%3}, [%4];"\
                 : "=r"((r)[0]), "=r"((r)[1]), "=r"((r)[2]), "=r"((r)[3])       \
                 : "r"(addr))

// HMMA: D(16x8,f32) += A(16x16,f16,row) * B(16x8,f16,col)
__device__ __forceinline__ void mma16816(float* d, const uint32_t* a, const uint32_t* b) {
    asm volatile(
        "mma.sync.aligned.m16n8k16.row.col.f32.f16.f16.f32 "
        "{%0,%1,%2,%3}, {%4,%5,%6,%7}, {%8,%9}, {%0,%1,%2,%3};"
        : "+f"(d[0]), "+f"(d[1]), "+f"(d[2]), "+f"(d[3])
        : "r"(a[0]), "r"(a[1]), "r"(a[2]), "r"(a[3]), "r"(b[0]), "r"(b[1]));
}

__device__ __forceinline__ void split2h(float v, __half& h, __half& l) {
    h = __float2half(v);
    l = __float2half(v - __half2float(h));
}
__device__ __forceinline__ uint32_t packh2(__half a, __half b) {
    __half2 p = __halves2half2(a, b);
    return *(uint32_t*)&p;
}

// ======================= conversion kernels ===================================
// also zeroes the kv/ksum accumulators (merged zero_acc)
__global__ __launch_bounds__(256) void convert_x_kernel(const float* __restrict__ x)
{
    size_t i = (size_t)blockIdx.x * 256 + threadIdx.x;   // float4 index
    float4 v = ((const float4*)x)[i];
    __half h[4];
    h[0] = __float2half(v.x); h[1] = __float2half(v.y);
    h[2] = __float2half(v.z); h[3] = __float2half(v.w);
    *(uint2*)&g_xh[4 * i] = *(uint2*)h;
    if (i < BH_SZ * HD_SZ * HD_SZ) g_kv[i] = 0.f;
    if (i < BH_SZ * HD_SZ)         g_ksum[i] = 0.f;
}

// transpose 4 weights to fp16: Wt[w][n][k] = W_w[k][n]
__global__ void convert_w_kernel(const float* __restrict__ Wq, const float* __restrict__ Wk,
                                 const float* __restrict__ Wv, const float* __restrict__ Wo)
{
    __shared__ float tile[32][33];
    const int w = blockIdx.z;
    const float* W = (w == 0) ? Wq : (w == 1) ? Wk : (w == 2) ? Wv : Wo;
    int tx = threadIdx.x, ty = threadIdx.y;
    int k = blockIdx.y * 32 + ty;
    int n = blockIdx.x * 32 + tx;
    tile[ty][tx] = W[k * D_SZ + n];
    __syncthreads();
    int nn = blockIdx.x * 32 + ty;
    int kk = blockIdx.y * 32 + tx;
    float v = tile[tx][ty];
    size_t idx = (size_t)w * D_SZ * D_SZ + (size_t)nn * D_SZ + kk;
    g_wt[idx] = __float2half(v);
}

// ======================= tensor-core GEMM (mma.sync fp16, single-term) ========
// CTA tile 128x128, BK=64, 256 threads (8 warps, 4x2), warp tile 32x64.
// 2-stage cp.async pipeline, R5-proven ordering. D = A*B, one HMMA per tile.
// MODE 0: fused QKV; q,k -> fp16 hi/lo (featmap), v -> fp16 hi/lo
// MODE 2: Wo (+bias, +resid) -> fp32
#define BKC     64
#define RSTRIDE 144          // bytes per smem row (64 fp16 + 16 pad)
#define A_BYTES (128 * RSTRIDE)
#define B_BYTES (128 * RSTRIDE)
#define AH_OFF  0
#define BH_OFF  (A_BYTES)
#define STAGE_BYTES (A_BYTES + B_BYTES)           // 36864
#define NSTAGE  2
#define NCHUNK  (D_SZ / BKC)                      // 8

template <int MODE>
__global__ __launch_bounds__(256, 2)
void gemm_tc(const __half* __restrict__ Ah,
             const __half* __restrict__ Bh,
             const float* __restrict__ b0p, const float* __restrict__ b1p,
             const float* __restrict__ b2p, const float* __restrict__ resid,
             float* __restrict__ C0)
{
    extern __shared__ __align__(16) char dsm[];
    const uint32_t sb = smem_u32(dsm);

    const int t    = threadIdx.x;
    const int lane = t & 31;
    const int wid  = t >> 5;
    const int wm   = wid >> 1;          // 0..3  (32-row group)
    const int wn   = wid & 1;           // 0..1  (64-col group)
    const int m0   = blockIdx.y * 128;
    const int n0   = blockIdx.x * 128;

    float acc[2][8][4];
#pragma unroll
    for (int i = 0; i < 2; i++)
#pragma unroll
        for (int j = 0; j < 8; j++)
#pragma unroll
            for (int r = 0; r < 4; r++) acc[i][j][r] = 0.f;

    const uint32_t aoff = (uint32_t)(wm * 32 + (lane & 15)) * RSTRIDE
                        + ((lane >> 4) & 1) * 16;
    const uint32_t boff = (uint32_t)(wn * 64 + (lane & 7) + ((lane >> 4) & 1) * 8) * RSTRIDE
                        + ((lane >> 3) & 1) * 16;

    // ---- async tile loader (BK=64: 128B per row, 8 x 16B parts) ----
    auto load_chunk = [&](int kc, int stage) {
        const uint32_t base = sb + stage * STAGE_BYTES;
        const size_t gkoff = (size_t)kc * BKC;
#pragma unroll
        for (int e = 0; e < 4; e++) {            // A: 128 rows x 8 parts = 1024
            int id   = t + e * 256;
            int row  = id >> 3;
            int part = id & 7;
            uint32_t doff = row * RSTRIDE + part * 16;
            size_t   goff = (size_t)(m0 + row) * D_SZ + gkoff + part * 8;
            cpa16(base + AH_OFF + doff, Ah + goff);
        }
#pragma unroll
        for (int e = 0; e < 4; e++) {            // B: 128 rows x 8 parts = 1024
            int id   = t + e * 256;
            int row  = id >> 3;
            int part = id & 7;
            uint32_t doff = row * RSTRIDE + part * 16;
            size_t   goff = (size_t)(n0 + row) * D_SZ + gkoff + part * 8;
            cpa16(base + BH_OFF + doff, Bh + goff);
        }
        CPA_COMMIT();
    };

    // ---- compute one BK=64 chunk (4 kk steps x 2 n-halves, single term) ----
    auto compute_chunk = [&](int stage) {
        const uint32_t base = sb + stage * STAGE_BYTES;
        const uint32_t aH = base + AH_OFF + aoff;
        const uint32_t bH = base + BH_OFF + boff;
#pragma unroll
        for (int kk = 0; kk < 4; kk++) {
            const int cb = kk * 32;
            uint32_t fah[2][4];
            LDSM4(fah[0], aH + cb);
            LDSM4(fah[1], aH + 16 * RSTRIDE + cb);
#pragma unroll
            for (int nh = 0; nh < 2; nh++) {
                const uint32_t bo2 = nh * 32 * RSTRIDE + cb;
                uint32_t fbh[2][4];
                LDSM4(fbh[0], bH + bo2);
                LDSM4(fbh[1], bH + bo2 + 16 * RSTRIDE);
#pragma unroll
                for (int mi = 0; mi < 2; mi++)
#pragma unroll
                    for (int nj = 0; nj < 4; nj++)
                        mma16816(acc[mi][nh * 4 + nj], fah[mi], &fbh[nj >> 1][(nj & 1) * 2]);
            }
        }
    };

    // ---- 2-stage pipeline, R5-proven ordering ----
    load_chunk(0, 0);
    for (int c = 0; c < NCHUNK; c++) {
        if (c + 1 < NCHUNK) {
            load_chunk(c + 1, (c + 1) & 1);
            CPA_WAIT(1);
        } else {
            CPA_WAIT(0);
        }
        __syncthreads();
        compute_chunk(c & 1);
        __syncthreads();
    }

    // ---- epilogue ----
    const int wsel = (MODE == 0) ? (n0 >> 9) : 0;
    const float* bias = (MODE == 0) ? ((wsel == 0) ? b0p : (wsel == 1) ? b1p : b2p) : b0p;
    const int ncol0 = (MODE == 0) ? (n0 & 511) : n0;

    const int g  = lane >> 2;
    const int tg = lane & 3;
#pragma unroll
    for (int mi = 0; mi < 2; mi++) {
#pragma unroll
        for (int half = 0; half < 2; half++) {
            int row = m0 + wm * 32 + mi * 16 + g + half * 8;
            const float* Rrow = (MODE == 2) ? (resid + (size_t)row * D_SZ) : nullptr;
#pragma unroll
            for (int nj = 0; nj < 8; nj++) {
                int col = ncol0 + wn * 64 + nj * 8 + tg * 2;
                float v0 = acc[mi][nj][half * 2 + 0] + bias[col];
                float v1 = acc[mi][nj][half * 2 + 1] + bias[col + 1];
                if (MODE == 0) {
                    if (wsel < 2) {   // feature map for q and k
                        v0 = (v0 > 0.f) ? (v0 + 1.f) : __expf(v0);
                        v1 = (v1 > 0.f) ? (v1 + 1.f) : __expf(v1);
                    }
                    size_t idx = (size_t)row * D_SZ + col;
                    __half h0, l0, h1, l1;
                    split2h(v0, h0, l0);
                    split2h(v1, h1, l1);
                    uint32_t hw = packh2(h0, h1), lw = packh2(l0, l1);
                    if (wsel == 0) {
                        *(uint32_t*)&g_qh[idx] = hw;
                        *(uint32_t*)&g_ql[idx] = lw;
                    } else if (wsel == 1) {
                        *(uint32_t*)&g_kh[idx] = hw;
                        *(uint32_t*)&g_kl[idx] = lw;
                    } else {
                        *(uint32_t*)&g_vh[idx] = hw;
                        *(uint32_t*)&g_vl[idx] = lw;
                    }
                } else {
                    v0 += Rrow[col];
                    v1 += Rrow[col + 1];
                    *(float2*)&C0[(size_t)row * D_SZ + col] = make_float2(v0, v1);
                }
            }
        }
    }
}

// ---------------- kv = K^T V per (b,h) via HMMA, plus k_sum --------------------
#define KVSTRIDE 144                       // bytes per smem row (64 fp16 + 8 pad)
__global__ __launch_bounds__(256)
void kv_kernel()
{
    __shared__ __half skh[64 * 72];
    __shared__ __half skl[64 * 72];
    __shared__ __half svh[64 * 72];
    __shared__ __half svl[64 * 72];

    const int bh    = blockIdx.y;
    const int chunk = blockIdx.x;          // 256-row chunk
    const int b = bh >> 3, h = bh & 7;
    const size_t tok0 = (size_t)b * S_SZ + chunk * 256;

    const int t    = threadIdx.x;
    const int lane = t & 31;
    const int wid  = t >> 5;
    const int d0   = (wid >> 1) * 16;
    const int m0   = (wid & 1) * 32;

    const uint32_t pkh = smem_u32(skh), pkl = smem_u32(skl);
    const uint32_t pvh = smem_u32(svh), pvl = smem_u32(svl);

    const uint32_t aoff = ((lane & 7) + ((lane >> 4) & 1) * 8) * KVSTRIDE
                        + d0 * 2 + ((lane >> 3) & 1) * 16;
    const uint32_t boff = ((lane & 7) + ((lane >> 3) & 1) * 8) * KVSTRIDE
                        + m0 * 2 + ((lane >> 4) & 1) * 16;

    float acc[4][4];
#pragma unroll
    for (int j = 0; j < 4; j++)
#pragma unroll
        for (int r = 0; r < 4; r++) acc[j][r] = 0.f;
    float ksl = 0.f;
    const int kcol  = t & 63;
    const int krow0 = (t >> 6) * 16;

    for (int it = 0; it < 4; it++) {       // 4 tiles of 64 rows
#pragma unroll
        for (int e = 0; e < 2; e++) {
            int id   = t + e * 256;
            int row  = id >> 3;
            int part = id & 7;
            uint32_t doff = row * KVSTRIDE + part * 16;
            size_t   goff = (tok0 + it * 64 + row) * D_SZ + h * HD_SZ + part * 8;
            cpa16(pkh + doff, g_kh + goff);
            cpa16(pkl + doff, g_kl + goff);
            cpa16(pvh + doff, g_vh + goff);
            cpa16(pvl + doff, g_vl + goff);
        }
        CPA_COMMIT();
        CPA_WAIT(0);
        __syncthreads();

#pragma unroll
        for (int r = 0; r < 16; r++) {
            int rr = krow0 + r;
            ksl += __half2float(skh[rr * 72 + kcol]) + __half2float(skl[rr * 72 + kcol]);
        }

#pragma unroll
        for (int ks = 0; ks < 4; ks++) {
            const uint32_t so = ks * 16 * KVSTRIDE;
            uint32_t akh[4], akl[4], bvh0[4], bvh1[4], bvl0[4], bvl1[4];
            LDSM4T(akh, pkh + aoff + so);
            LDSM4T(akl, pkl + aoff + so);
            LDSM4T(bvh0, pvh + boff + so);
            LDSM4T(bvh1, pvh + boff + so + 32);
            LDSM4T(bvl0, pvl + boff + so);
            LDSM4T(bvl1, pvl + boff + so + 32);
#pragma unroll
            for (int j = 0; j < 4; j++) {
                const uint32_t* bh2 = (j < 2) ? &bvh0[(j & 1) * 2] : &bvh1[(j & 1) * 2];
                const uint32_t* bl2 = (j < 2) ? &bvl0[(j & 1) * 2] : &bvl1[(j & 1) * 2];
                mma16816(acc[j], akh, bh2);
                mma16816(acc[j], akh, bl2);
                mma16816(acc[j], akl, bh2);
            }
        }
        __syncthreads();
    }

    float* kvdst = g_kv + bh * (HD_SZ * HD_SZ);
    const int g  = lane >> 2;
    const int tg = lane & 3;
#pragma unroll
    for (int j = 0; j < 4; j++) {
        int col = m0 + j * 8 + tg * 2;
        atomicAdd(&kvdst[(d0 + g) * HD_SZ + col],         acc[j][0]);
        atomicAdd(&kvdst[(d0 + g) * HD_SZ + col + 1],     acc[j][1]);
        atomicAdd(&kvdst[(d0 + g + 8) * HD_SZ + col],     acc[j][2]);
        atomicAdd(&kvdst[(d0 + g + 8) * HD_SZ + col + 1], acc[j][3]);
    }
    atomicAdd(&g_ksum[bh * HD_SZ + kcol], ksl);
}

// ---------------- out = (q @ kv) / max(q . ksum, 1e-6) via HMMA ----------------
__global__ __launch_bounds__(256)
void attn_kernel()
{
    __shared__ __half sqh[64 * 72];
    __shared__ __half sql[64 * 72];
    __shared__ __half skvh[64 * 72];
    __shared__ __half skvl[64 * 72];
    __shared__ float ksb[64];
    __shared__ float nrm[64];

    const int bh   = blockIdx.y;
    const int tile = blockIdx.x;
    const int b = bh >> 3, h = bh & 7;
    const size_t tok0 = (size_t)b * S_SZ + tile * 64;

    const int t    = threadIdx.x;
    const int lane = t & 31;
    const int wid  = t >> 5;
    const int wm   = wid >> 1;
    const int wn   = wid & 1;

    const uint32_t pqh = smem_u32(sqh), pql = smem_u32(sql);
    const uint32_t pkvh = smem_u32(skvh), pkvl = smem_u32(skvl);

#pragma unroll
    for (int e = 0; e < 2; e++) {
        int id   = t + e * 256;
        int row  = id >> 3;
        int part = id & 7;
        uint32_t doff = row * KVSTRIDE + part * 16;
        size_t   goff = (tok0 + row) * D_SZ + h * HD_SZ + part * 8;
        cpa16(pqh + doff, g_qh + goff);
        cpa16(pql + doff, g_ql + goff);
    }
    CPA_COMMIT();

    const float* kvsrc = g_kv + bh * 4096;
#pragma unroll
    for (int e = 0; e < 4; e++) {
        int i4 = t + e * 256;
        int r  = i4 >> 4;
        int c4 = (i4 & 15) << 2;
        float4 v = *(const float4*)&kvsrc[r * 64 + c4];
        __half hh[4], ll[4];
        split2h(v.x, hh[0], ll[0]); split2h(v.y, hh[1], ll[1]);
        split2h(v.z, hh[2], ll[2]); split2h(v.w, hh[3], ll[3]);
        *(uint2*)&skvh[r * 72 + c4] = *(uint2*)hh;
        *(uint2*)&skvl[r * 72 + c4] = *(uint2*)ll;
    }
    if (t < 64) ksb[t] = g_ksum[bh * HD_SZ + t];
    CPA_WAIT(0);
    __syncthreads();

    if (t < 64) {
        float s = 0.f;
#pragma unroll
        for (int d = 0; d < 64; d++) {
            float qv = __half2float(sqh[t * 72 + d]) + __half2float(sql[t * 72 + d]);
            s = fmaf(qv, ksb[d], s);
        }
        nrm[t] = fmaxf(s, 1e-6f);
    }
    __syncthreads();

    const uint32_t aoff = (uint32_t)(wm * 16 + (lane & 15)) * KVSTRIDE
                        + ((lane >> 4) & 1) * 16;
    const uint32_t boff = ((lane & 7) + ((lane >> 3) & 1) * 8) * KVSTRIDE
                        + (wn * 32) * 2 + ((lane >> 4) & 1) * 16;

    float acc[4][4];
#pragma unroll
    for (int j = 0; j < 4; j++)
#pragma unroll
        for (int r = 0; r < 4; r++) acc[j][r] = 0.f;

#pragma unroll
    for (int ks = 0; ks < 4; ks++) {
        const uint32_t acb = ks * 32;
        const uint32_t so  = ks * 16 * KVSTRIDE;
        uint32_t fqh[4], fql[4], fbh0[4], fbh1[4], fbl0[4], fbl1[4];
        LDSM4(fqh, pqh + aoff + acb);
        LDSM4(fql, pql + aoff + acb);
        LDSM4T(fbh0, pkvh + boff + so);
        LDSM4T(fbh1, pkvh + boff + so + 32);
        LDSM4T(fbl0, pkvl + boff + so);
        LDSM4T(fbl1, pkvl + boff + so + 32);
#pragma unroll
        for (int j = 0; j < 4; j++) {
            const uint32_t* bh2 = (j < 2) ? &fbh0[(j & 1) * 2] : &fbh1[(j & 1) * 2];
            const uint32_t* bl2 = (j < 2) ? &fbl0[(j & 1) * 2] : &fbl1[(j & 1) * 2];
            mma16816(acc[j], fqh, bh2);
            mma16816(acc[j], fql, bh2);
            mma16816(acc[j], fqh, bl2);
        }
    }

    const int g  = lane >> 2;
    const int tg = lane & 3;
#pragma unroll
    for (int half = 0; half < 2; half++) {
        int r = wm * 16 + g + half * 8;
        float inv = 1.0f / nrm[r];
        size_t rbase = (tok0 + r) * D_SZ + h * HD_SZ;
#pragma unroll
        for (int j = 0; j < 4; j++) {
            int col = wn * 32 + j * 8 + tg * 2;
            float v0 = acc[j][half * 2 + 0] * inv;
            float v1 = acc[j][half * 2 + 1] * inv;
            *(uint32_t*)&g_ah[rbase + col] = packh2(__float2half(v0), __float2half(v1));
        }
    }
}

// ---------------- LayerNorm over g_y -> out (float4) --------------------------
__global__ __launch_bounds__(256)
void ln_kernel(const float* __restrict__ gamma, const float* __restrict__ beta,
               float* __restrict__ out)
{
    const int row  = blockIdx.x * 8 + (threadIdx.x >> 5);
    const int lane = threadIdx.x & 31;
    const float4* y4 = (const float4*)(g_y + (size_t)row * D_SZ);

    float4 vals[4];
    float s = 0.f, s2 = 0.f;
#pragma unroll
    for (int i = 0; i < 4; i++) {
        float4 v = y4[lane + i * 32];
        vals[i] = v;
        s += v.x + v.y + v.z + v.w;
        s2 = fmaf(v.x, v.x, s2); s2 = fmaf(v.y, v.y, s2);
        s2 = fmaf(v.z, v.z, s2); s2 = fmaf(v.w, v.w, s2);
    }
#pragma unroll
    for (int o = 16; o > 0; o >>= 1) {
        s  += __shfl_xor_sync(0xFFFFFFFFu, s, o);
        s2 += __shfl_xor_sync(0xFFFFFFFFu, s2, o);
    }
    const float mean = s * (1.0f / 512.0f);
    const float var  = s2 * (1.0f / 512.0f) - mean * mean;
    const float inv  = rsqrtf(var + 1e-5f);

    const float4* g4 = (const float4*)gamma;
    const float4* b4 = (const float4*)beta;
    float4* o4 = (float4*)(out + (size_t)row * D_SZ);
#pragma unroll
    for (int i = 0; i < 4; i++) {
        int c = lane + i * 32;
        float4 g = g4[c], bb = b4[c], v = vals[i];
        float4 r;
        r.x = (v.x - mean) * inv * g.x + bb.x;
        r.y = (v.y - mean) * inv * g.y + bb.y;
        r.z = (v.z - mean) * inv * g.z + bb.z;
        r.w = (v.w - mean) * inv * g.w + bb.w;
        o4[c] = r;
    }
}

// ---------------- launch ------------------------------------------------------
extern "C" void kernel_launch(void* const* d_in, const int* in_sizes, int n_in,
                              void* d_out, int out_size)
{
    const float* x     = (const float*)d_in[0];
    const float* Wq    = (const float*)d_in[1];
    const float* bq    = (const float*)d_in[2];
    const float* Wk    = (const float*)d_in[3];
    const float* bk    = (const float*)d_in[4];
    const float* Wv    = (const float*)d_in[5];
    const float* bv    = (const float*)d_in[6];
    const float* Wo    = (const float*)d_in[7];
    const float* bo    = (const float*)d_in[8];
    const float* gamma = (const float*)d_in[9];
    const float* beta  = (const float*)d_in[10];
    float* out = (float*)d_out;

    __half *pxh, *pwt, *pah;
    float *py;
    cudaGetSymbolAddress((void**)&pxh, g_xh);
    cudaGetSymbolAddress((void**)&pwt, g_wt);
    cudaGetSymbolAddress((void**)&pah, g_ah);
    cudaGetSymbolAddress((void**)&py,  g_y);

    const int SMEM_DYN = NSTAGE * STAGE_BYTES;   // 73728
    cudaFuncSetAttribute(gemm_tc<0>, cudaFuncAttributeMaxDynamicSharedMemorySize, SMEM_DYN);
    cudaFuncSetAttribute(gemm_tc<2>, cudaFuncAttributeMaxDynamicSharedMemorySize, SMEM_DYN);

    // x to fp16 (+ zero kv/ksum accumulators), weights to fp16
    convert_x_kernel<<<(N_TOK * D_SZ / 4) / 256, 256>>>(x);
    convert_w_kernel<<<dim3(16, 16, 4), dim3(32, 32)>>>(Wq, Wk, Wv, Wo);

    // fused QKV projection: N_total = 1536 over [Wq|Wk|Wv]
    dim3 gqkv(3 * D_SZ / 128, N_TOK / 128);   // (12, 256)
    gemm_tc<0><<<gqkv, 256, SMEM_DYN>>>(pxh, pwt,
                                        bq, bk, bv, nullptr, nullptr);

    // kv summary + k_sum (tensor cores)
    kv_kernel<<<dim3(S_SZ / 256, BH_SZ), 256>>>();

    // normalized attention output (tensor cores, emits fp16)
    attn_kernel<<<dim3(S_SZ / 64, BH_SZ), 256>>>();

    // output projection + residual
    dim3 gwo(D_SZ / 128, N_TOK / 128);        // (4, 256)
    gemm_tc<2><<<gwo, 256, SMEM_DYN>>>(pah, pwt + 3 * D_SZ * D_SZ,
                                       bo, nullptr, nullptr, x, py);

    // layernorm
    ln_kernel<<<N_TOK / 8, 256>>>(gamma, beta, out);
}

// round 16
// speedup vs baseline: 1.6981x; 1.1747x over previous
#include <cuda_runtime.h>
#include <cuda_fp16.h>
#include <cstdint>
#include <math.h>

// Problem constants
#define B_SZ   4
#define S_SZ   8192
#define D_SZ   512
#define H_SZ   8
#define HD_SZ  64
#define N_TOK  (B_SZ * S_SZ)          // 32768
#define BH_SZ  (B_SZ * H_SZ)          // 32

// ---------------- scratch (static __device__, no allocations) ----------------
__device__ __half g_xh[(size_t)N_TOK * D_SZ];
__device__ __half g_wt[4 * D_SZ * D_SZ];          // transposed weights, fp16
__device__ __half g_qh[(size_t)N_TOK * D_SZ];     // feature-mapped q, fp16
__device__ __half g_kh[(size_t)N_TOK * D_SZ];     // feature-mapped k, fp16
__device__ __half g_vh[(size_t)N_TOK * D_SZ];     // v, fp16
__device__ __half g_ah[(size_t)N_TOK * D_SZ];     // attention output, fp16
__device__ float  g_y[(size_t)N_TOK * D_SZ];
__device__ float  g_kv[BH_SZ * HD_SZ * HD_SZ];
__device__ float  g_ksum[BH_SZ * HD_SZ];

// ======================= helpers ==============================================
__device__ __forceinline__ uint32_t smem_u32(const void* p) {
    uint32_t a;
    asm("{ .reg .u64 t; cvta.to.shared.u64 t, %1; cvt.u32.u64 %0, t; }"
        : "=r"(a) : "l"(p));
    return a;
}
__device__ __forceinline__ void cpa16(uint32_t dst, const void* src) {
    asm volatile("cp.async.cg.shared.global [%0], [%1], 16;" :: "r"(dst), "l"(src));
}
#define CPA_COMMIT() asm volatile("cp.async.commit_group;" ::: "memory")
#define CPA_WAIT(n)  asm volatile("cp.async.wait_group %0;" :: "n"(n) : "memory")

#define LDSM4(r, addr)                                                          \
    asm volatile("ldmatrix.sync.aligned.m8n8.x4.shared.b16 {%0,%1,%2,%3}, [%4];"\
                 : "=r"((r)[0]), "=r"((r)[1]), "=r"((r)[2]), "=r"((r)[3])       \
                 : "r"(addr))
#define LDSM4T(r, addr)                                                         \
    asm volatile("ldmatrix.sync.aligned.m8n8.x4.trans.shared.b16 {%0,%1,%2,%3}, [%4];"\
                 : "=r"((r)[0]), "=r"((r)[1]), "=r"((r)[2]), "=r"((r)[3])       \
                 : "r"(addr))

// HMMA: D(16x8,f32) += A(16x16,f16,row) * B(16x8,f16,col)
__device__ __forceinline__ void mma16816(float* d, const uint32_t* a, const uint32_t* b) {
    asm volatile(
        "mma.sync.aligned.m16n8k16.row.col.f32.f16.f16.f32 "
        "{%0,%1,%2,%3}, {%4,%5,%6,%7}, {%8,%9}, {%0,%1,%2,%3};"
        : "+f"(d[0]), "+f"(d[1]), "+f"(d[2]), "+f"(d[3])
        : "r"(a[0]), "r"(a[1]), "r"(a[2]), "r"(a[3]), "r"(b[0]), "r"(b[1]));
}

__device__ __forceinline__ void split2h(float v, __half& h, __half& l) {
    h = __float2half(v);
    l = __float2half(v - __half2float(h));
}
__device__ __forceinline__ uint32_t packh2(__half a, __half b) {
    __half2 p = __halves2half2(a, b);
    return *(uint32_t*)&p;
}

// ======================= conversion kernels ===================================
// also zeroes the kv/ksum accumulators (merged zero_acc)
__global__ __launch_bounds__(256) void convert_x_kernel(const float* __restrict__ x)
{
    size_t i = (size_t)blockIdx.x * 256 + threadIdx.x;   // float4 index
    float4 v = ((const float4*)x)[i];
    __half h[4];
    h[0] = __float2half(v.x); h[1] = __float2half(v.y);
    h[2] = __float2half(v.z); h[3] = __float2half(v.w);
    *(uint2*)&g_xh[4 * i] = *(uint2*)h;
    if (i < BH_SZ * HD_SZ * HD_SZ) g_kv[i] = 0.f;
    if (i < BH_SZ * HD_SZ)         g_ksum[i] = 0.f;
}

// transpose 4 weights to fp16: Wt[w][n][k] = W_w[k][n]
__global__ void convert_w_kernel(const float* __restrict__ Wq, const float* __restrict__ Wk,
                                 const float* __restrict__ Wv, const float* __restrict__ Wo)
{
    __shared__ float tile[32][33];
    const int w = blockIdx.z;
    const float* W = (w == 0) ? Wq : (w == 1) ? Wk : (w == 2) ? Wv : Wo;
    int tx = threadIdx.x, ty = threadIdx.y;
    int k = blockIdx.y * 32 + ty;
    int n = blockIdx.x * 32 + tx;
    tile[ty][tx] = W[k * D_SZ + n];
    __syncthreads();
    int nn = blockIdx.x * 32 + ty;
    int kk = blockIdx.y * 32 + tx;
    float v = tile[tx][ty];
    size_t idx = (size_t)w * D_SZ * D_SZ + (size_t)nn * D_SZ + kk;
    g_wt[idx] = __float2half(v);
}

// ======================= tensor-core GEMM (mma.sync fp16, single-term) ========
// CTA tile 128x128, BK=64, 256 threads (8 warps, 4x2), warp tile 32x64.
// 2-stage cp.async pipeline, R5-proven ordering. D = A*B, one HMMA per tile.
// MODE 0: fused QKV; q,k (featmap), v -> single fp16
// MODE 2: Wo (+bias, +resid) -> fp32
#define BKC     64
#define RSTRIDE 144          // bytes per smem row (64 fp16 + 16 pad)
#define A_BYTES (128 * RSTRIDE)
#define B_BYTES (128 * RSTRIDE)
#define AH_OFF  0
#define BH_OFF  (A_BYTES)
#define STAGE_BYTES (A_BYTES + B_BYTES)           // 36864
#define NSTAGE  2
#define NCHUNK  (D_SZ / BKC)                      // 8

template <int MODE>
__global__ __launch_bounds__(256, 2)
void gemm_tc(const __half* __restrict__ Ah,
             const __half* __restrict__ Bh,
             const float* __restrict__ b0p, const float* __restrict__ b1p,
             const float* __restrict__ b2p, const float* __restrict__ resid,
             float* __restrict__ C0)
{
    extern __shared__ __align__(16) char dsm[];
    const uint32_t sb = smem_u32(dsm);

    const int t    = threadIdx.x;
    const int lane = t & 31;
    const int wid  = t >> 5;
    const int wm   = wid >> 1;          // 0..3  (32-row group)
    const int wn   = wid & 1;           // 0..1  (64-col group)
    const int m0   = blockIdx.y * 128;
    const int n0   = blockIdx.x * 128;

    float acc[2][8][4];
#pragma unroll
    for (int i = 0; i < 2; i++)
#pragma unroll
        for (int j = 0; j < 8; j++)
#pragma unroll
            for (int r = 0; r < 4; r++) acc[i][j][r] = 0.f;

    const uint32_t aoff = (uint32_t)(wm * 32 + (lane & 15)) * RSTRIDE
                        + ((lane >> 4) & 1) * 16;
    const uint32_t boff = (uint32_t)(wn * 64 + (lane & 7) + ((lane >> 4) & 1) * 8) * RSTRIDE
                        + ((lane >> 3) & 1) * 16;

    // ---- async tile loader (BK=64: 128B per row, 8 x 16B parts) ----
    auto load_chunk = [&](int kc, int stage) {
        const uint32_t base = sb + stage * STAGE_BYTES;
        const size_t gkoff = (size_t)kc * BKC;
#pragma unroll
        for (int e = 0; e < 4; e++) {            // A: 128 rows x 8 parts = 1024
            int id   = t + e * 256;
            int row  = id >> 3;
            int part = id & 7;
            uint32_t doff = row * RSTRIDE + part * 16;
            size_t   goff = (size_t)(m0 + row) * D_SZ + gkoff + part * 8;
            cpa16(base + AH_OFF + doff, Ah + goff);
        }
#pragma unroll
        for (int e = 0; e < 4; e++) {            // B: 128 rows x 8 parts = 1024
            int id   = t + e * 256;
            int row  = id >> 3;
            int part = id & 7;
            uint32_t doff = row * RSTRIDE + part * 16;
            size_t   goff = (size_t)(n0 + row) * D_SZ + gkoff + part * 8;
            cpa16(base + BH_OFF + doff, Bh + goff);
        }
        CPA_COMMIT();
    };

    // ---- compute one BK=64 chunk (4 kk steps x 2 n-halves, single term) ----
    auto compute_chunk = [&](int stage) {
        const uint32_t base = sb + stage * STAGE_BYTES;
        const uint32_t aH = base + AH_OFF + aoff;
        const uint32_t bH = base + BH_OFF + boff;
#pragma unroll
        for (int kk = 0; kk < 4; kk++) {
            const int cb = kk * 32;
            uint32_t fah[2][4];
            LDSM4(fah[0], aH + cb);
            LDSM4(fah[1], aH + 16 * RSTRIDE + cb);
#pragma unroll
            for (int nh = 0; nh < 2; nh++) {
                const uint32_t bo2 = nh * 32 * RSTRIDE + cb;
                uint32_t fbh[2][4];
                LDSM4(fbh[0], bH + bo2);
                LDSM4(fbh[1], bH + bo2 + 16 * RSTRIDE);
#pragma unroll
                for (int mi = 0; mi < 2; mi++)
#pragma unroll
                    for (int nj = 0; nj < 4; nj++)
                        mma16816(acc[mi][nh * 4 + nj], fah[mi], &fbh[nj >> 1][(nj & 1) * 2]);
            }
        }
    };

    // ---- 2-stage pipeline, R5-proven ordering ----
    load_chunk(0, 0);
    for (int c = 0; c < NCHUNK; c++) {
        if (c + 1 < NCHUNK) {
            load_chunk(c + 1, (c + 1) & 1);
            CPA_WAIT(1);
        } else {
            CPA_WAIT(0);
        }
        __syncthreads();
        compute_chunk(c & 1);
        __syncthreads();
    }

    // ---- epilogue ----
    const int wsel = (MODE == 0) ? (n0 >> 9) : 0;
    const float* bias = (MODE == 0) ? ((wsel == 0) ? b0p : (wsel == 1) ? b1p : b2p) : b0p;
    const int ncol0 = (MODE == 0) ? (n0 & 511) : n0;

    const int g  = lane >> 2;
    const int tg = lane & 3;
#pragma unroll
    for (int mi = 0; mi < 2; mi++) {
#pragma unroll
        for (int half = 0; half < 2; half++) {
            int row = m0 + wm * 32 + mi * 16 + g + half * 8;
            const float* Rrow = (MODE == 2) ? (resid + (size_t)row * D_SZ) : nullptr;
#pragma unroll
            for (int nj = 0; nj < 8; nj++) {
                int col = ncol0 + wn * 64 + nj * 8 + tg * 2;
                float v0 = acc[mi][nj][half * 2 + 0] + bias[col];
                float v1 = acc[mi][nj][half * 2 + 1] + bias[col + 1];
                if (MODE == 0) {
                    if (wsel < 2) {   // feature map for q and k
                        v0 = (v0 > 0.f) ? (v0 + 1.f) : __expf(v0);
                        v1 = (v1 > 0.f) ? (v1 + 1.f) : __expf(v1);
                    }
                    size_t idx = (size_t)row * D_SZ + col;
                    uint32_t hw = packh2(__float2half(v0), __float2half(v1));
                    if (wsel == 0)      *(uint32_t*)&g_qh[idx] = hw;
                    else if (wsel == 1) *(uint32_t*)&g_kh[idx] = hw;
                    else                *(uint32_t*)&g_vh[idx] = hw;
                } else {
                    v0 += Rrow[col];
                    v1 += Rrow[col + 1];
                    *(float2*)&C0[(size_t)row * D_SZ + col] = make_float2(v0, v1);
                }
            }
        }
    }
}

// ---------------- kv = K^T V per (b,h) via HMMA, plus k_sum --------------------
// single fp16 term: kv = fp16(k)^T fp16(v)
#define KVSTRIDE 144                       // bytes per smem row (64 fp16 + 8 pad)
__global__ __launch_bounds__(256)
void kv_kernel()
{
    __shared__ __half skh[64 * 72];
    __shared__ __half svh[64 * 72];

    const int bh    = blockIdx.y;
    const int chunk = blockIdx.x;          // 256-row chunk
    const int b = bh >> 3, h = bh & 7;
    const size_t tok0 = (size_t)b * S_SZ + chunk * 256;

    const int t    = threadIdx.x;
    const int lane = t & 31;
    const int wid  = t >> 5;
    const int d0   = (wid >> 1) * 16;
    const int m0   = (wid & 1) * 32;

    const uint32_t pkh = smem_u32(skh);
    const uint32_t pvh = smem_u32(svh);

    const uint32_t aoff = ((lane & 7) + ((lane >> 4) & 1) * 8) * KVSTRIDE
                        + d0 * 2 + ((lane >> 3) & 1) * 16;
    const uint32_t boff = ((lane & 7) + ((lane >> 3) & 1) * 8) * KVSTRIDE
                        + m0 * 2 + ((lane >> 4) & 1) * 16;

    float acc[4][4];
#pragma unroll
    for (int j = 0; j < 4; j++)
#pragma unroll
        for (int r = 0; r < 4; r++) acc[j][r] = 0.f;
    float ksl = 0.f;
    const int kcol  = t & 63;
    const int krow0 = (t >> 6) * 16;

    for (int it = 0; it < 4; it++) {       // 4 tiles of 64 rows
#pragma unroll
        for (int e = 0; e < 2; e++) {
            int id   = t + e * 256;
            int row  = id >> 3;
            int part = id & 7;
            uint32_t doff = row * KVSTRIDE + part * 16;
            size_t   goff = (tok0 + it * 64 + row) * D_SZ + h * HD_SZ + part * 8;
            cpa16(pkh + doff, g_kh + goff);
            cpa16(pvh + doff, g_vh + goff);
        }
        CPA_COMMIT();
        CPA_WAIT(0);
        __syncthreads();

#pragma unroll
        for (int r = 0; r < 16; r++) {
            int rr = krow0 + r;
            ksl += __half2float(skh[rr * 72 + kcol]);
        }

#pragma unroll
        for (int ks = 0; ks < 4; ks++) {
            const uint32_t so = ks * 16 * KVSTRIDE;
            uint32_t akh[4], bvh0[4], bvh1[4];
            LDSM4T(akh, pkh + aoff + so);
            LDSM4T(bvh0, pvh + boff + so);
            LDSM4T(bvh1, pvh + boff + so + 32);
#pragma unroll
            for (int j = 0; j < 4; j++) {
                const uint32_t* bh2 = (j < 2) ? &bvh0[(j & 1) * 2] : &bvh1[(j & 1) * 2];
                mma16816(acc[j], akh, bh2);
            }
        }
        __syncthreads();
    }

    float* kvdst = g_kv + bh * (HD_SZ * HD_SZ);
    const int g  = lane >> 2;
    const int tg = lane & 3;
#pragma unroll
    for (int j = 0; j < 4; j++) {
        int col = m0 + j * 8 + tg * 2;
        atomicAdd(&kvdst[(d0 + g) * HD_SZ + col],         acc[j][0]);
        atomicAdd(&kvdst[(d0 + g) * HD_SZ + col + 1],     acc[j][1]);
        atomicAdd(&kvdst[(d0 + g + 8) * HD_SZ + col],     acc[j][2]);
        atomicAdd(&kvdst[(d0 + g + 8) * HD_SZ + col + 1], acc[j][3]);
    }
    atomicAdd(&g_ksum[bh * HD_SZ + kcol], ksl);
}

// ---------------- out = (q @ kv) / max(q . ksum, 1e-6) via HMMA ----------------
// q single fp16; kv fp32 -> fp16 hi/lo in smem (2 MMA terms, free compute)
__global__ __launch_bounds__(256)
void attn_kernel()
{
    __shared__ __half sqh[64 * 72];
    __shared__ __half skvh[64 * 72];
    __shared__ __half skvl[64 * 72];
    __shared__ float ksb[64];
    __shared__ float nrm[64];

    const int bh   = blockIdx.y;
    const int tile = blockIdx.x;
    const int b = bh >> 3, h = bh & 7;
    const size_t tok0 = (size_t)b * S_SZ + tile * 64;

    const int t    = threadIdx.x;
    const int lane = t & 31;
    const int wid  = t >> 5;
    const int wm   = wid >> 1;
    const int wn   = wid & 1;

    const uint32_t pqh = smem_u32(sqh);
    const uint32_t pkvh = smem_u32(skvh), pkvl = smem_u32(skvl);

    {
        int row  = t >> 2;
        int part = t & 3;
        // 64 rows x 4 parts(16B)... need 8 parts per row: use 2 tasks/thread
#pragma unroll
        for (int e = 0; e < 2; e++) {
            int id = t + e * 256;
            int r  = id >> 3;
            int p  = id & 7;
            uint32_t doff = r * KVSTRIDE + p * 16;
            size_t   goff = (tok0 + r) * D_SZ + h * HD_SZ + p * 8;
            cpa16(pqh + doff, g_qh + goff);
        }
        (void)row; (void)part;
    }
    CPA_COMMIT();

    const float* kvsrc = g_kv + bh * 4096;
#pragma unroll
    for (int e = 0; e < 4; e++) {
        int i4 = t + e * 256;
        int r  = i4 >> 4;
        int c4 = (i4 & 15) << 2;
        float4 v = *(const float4*)&kvsrc[r * 64 + c4];
        __half hh[4], ll[4];
        split2h(v.x, hh[0], ll[0]); split2h(v.y, hh[1], ll[1]);
        split2h(v.z, hh[2], ll[2]); split2h(v.w, hh[3], ll[3]);
        *(uint2*)&skvh[r * 72 + c4] = *(uint2*)hh;
        *(uint2*)&skvl[r * 72 + c4] = *(uint2*)ll;
    }
    if (t < 64) ksb[t] = g_ksum[bh * HD_SZ + t];
    CPA_WAIT(0);
    __syncthreads();

    if (t < 64) {
        float s = 0.f;
#pragma unroll
        for (int d = 0; d < 64; d++) {
            float qv = __half2float(sqh[t * 72 + d]);
            s = fmaf(qv, ksb[d], s);
        }
        nrm[t] = fmaxf(s, 1e-6f);
    }
    __syncthreads();

    const uint32_t aoff = (uint32_t)(wm * 16 + (lane & 15)) * KVSTRIDE
                        + ((lane >> 4) & 1) * 16;
    const uint32_t boff = ((lane & 7) + ((lane >> 3) & 1) * 8) * KVSTRIDE
                        + (wn * 32) * 2 + ((lane >> 4) & 1) * 16;

    float acc[4][4];
#pragma unroll
    for (int j = 0; j < 4; j++)
#pragma unroll
        for (int r = 0; r < 4; r++) acc[j][r] = 0.f;

#pragma unroll
    for (int ks = 0; ks < 4; ks++) {
        const uint32_t acb = ks * 32;
        const uint32_t so  = ks * 16 * KVSTRIDE;
        uint32_t fqh[4], fbh0[4], fbh1[4], fbl0[4], fbl1[4];
        LDSM4(fqh, pqh + aoff + acb);
        LDSM4T(fbh0, pkvh + boff + so);
        LDSM4T(fbh1, pkvh + boff + so + 32);
        LDSM4T(fbl0, pkvl + boff + so);
        LDSM4T(fbl1, pkvl + boff + so + 32);
#pragma unroll
        for (int j = 0; j < 4; j++) {
            const uint32_t* bh2 = (j < 2) ? &fbh0[(j & 1) * 2] : &fbh1[(j & 1) * 2];
            const uint32_t* bl2 = (j < 2) ? &fbl0[(j & 1) * 2] : &fbl1[(j & 1) * 2];
            mma16816(acc[j], fqh, bh2);
            mma16816(acc[j], fqh, bl2);
        }
    }

    const int g  = lane >> 2;
    const int tg = lane & 3;
#pragma unroll
    for (int half = 0; half < 2; half++) {
        int r = wm * 16 + g + half * 8;
        float inv = 1.0f / nrm[r];
        size_t rbase = (tok0 + r) * D_SZ + h * HD_SZ;
#pragma unroll
        for (int j = 0; j < 4; j++) {
            int col = wn * 32 + j * 8 + tg * 2;
            float v0 = acc[j][half * 2 + 0] * inv;
            float v1 = acc[j][half * 2 + 1] * inv;
            *(uint32_t*)&g_ah[rbase + col] = packh2(__float2half(v0), __float2half(v1));
        }
    }
}

// ---------------- LayerNorm over g_y -> out (float4) --------------------------
__global__ __launch_bounds__(256)
void ln_kernel(const float* __restrict__ gamma, const float* __restrict__ beta,
               float* __restrict__ out)
{
    const int row  = blockIdx.x * 8 + (threadIdx.x >> 5);
    const int lane = threadIdx.x & 31;
    const float4* y4 = (const float4*)(g_y + (size_t)row * D_SZ);

    float4 vals[4];
    float s = 0.f, s2 = 0.f;
#pragma unroll
    for (int i = 0; i < 4; i++) {
        float4 v = y4[lane + i * 32];
        vals[i] = v;
        s += v.x + v.y + v.z + v.w;
        s2 = fmaf(v.x, v.x, s2); s2 = fmaf(v.y, v.y, s2);
        s2 = fmaf(v.z, v.z, s2); s2 = fmaf(v.w, v.w, s2);
    }
#pragma unroll
    for (int o = 16; o > 0; o >>= 1) {
        s  += __shfl_xor_sync(0xFFFFFFFFu, s, o);
        s2 += __shfl_xor_sync(0xFFFFFFFFu, s2, o);
    }
    const float mean = s * (1.0f / 512.0f);
    const float var  = s2 * (1.0f / 512.0f) - mean * mean;
    const float inv  = rsqrtf(var + 1e-5f);

    const float4* g4 = (const float4*)gamma;
    const float4* b4 = (const float4*)beta;
    float4* o4 = (float4*)(out + (size_t)row * D_SZ);
#pragma unroll
    for (int i = 0; i < 4; i++) {
        int c = lane + i * 32;
        float4 g = g4[c], bb = b4[c], v = vals[i];
        float4 r;
        r.x = (v.x - mean) * inv * g.x + bb.x;
        r.y = (v.y - mean) * inv * g.y + bb.y;
        r.z = (v.z - mean) * inv * g.z + bb.z;
        r.w = (v.w - mean) * inv * g.w + bb.w;
        o4[c] = r;
    }
}

// ---------------- launch ------------------------------------------------------
extern "C" void kernel_launch(void* const* d_in, const int* in_sizes, int n_in,
                              void* d_out, int out_size)
{
    const float* x     = (const float*)d_in[0];
    const float* Wq    = (const float*)d_in[1];
    const float* bq    = (const float*)d_in[2];
    const float* Wk    = (const float*)d_in[3];
    const float* bk    = (const float*)d_in[4];
    const float* Wv    = (const float*)d_in[5];
    const float* bv    = (const float*)d_in[6];
    const float* Wo    = (const float*)d_in[7];
    const float* bo    = (const float*)d_in[8];
    const float* gamma = (const float*)d_in[9];
    const float* beta  = (const float*)d_in[10];
    float* out = (float*)d_out;

    __half *pxh, *pwt, *pah;
    float *py;
    cudaGetSymbolAddress((void**)&pxh, g_xh);
    cudaGetSymbolAddress((void**)&pwt, g_wt);
    cudaGetSymbolAddress((void**)&pah, g_ah);
    cudaGetSymbolAddress((void**)&py,  g_y);

    const int SMEM_DYN = NSTAGE * STAGE_BYTES;   // 73728
    cudaFuncSetAttribute(gemm_tc<0>, cudaFuncAttributeMaxDynamicSharedMemorySize, SMEM_DYN);
    cudaFuncSetAttribute(gemm_tc<2>, cudaFuncAttributeMaxDynamicSharedMemorySize, SMEM_DYN);

    // x to fp16 (+ zero kv/ksum accumulators), weights to fp16
    convert_x_kernel<<<(N_TOK * D_SZ / 4) / 256, 256>>>(x);
    convert_w_kernel<<<dim3(16, 16, 4), dim3(32, 32)>>>(Wq, Wk, Wv, Wo);

    // fused QKV projection: N_total = 1536 over [Wq|Wk|Wv]
    dim3 gqkv(3 * D_SZ / 128, N_TOK / 128);   // (12, 256)
    gemm_tc<0><<<gqkv, 256, SMEM_DYN>>>(pxh, pwt,
                                        bq, bk, bv, nullptr, nullptr);

    // kv summary + k_sum (tensor cores)
    kv_kernel<<<dim3(S_SZ / 256, BH_SZ), 256>>>();

    // normalized attention output (tensor cores)
    attn_kernel<<<dim3(S_SZ / 64, BH_SZ), 256>>>();

    // output projection + residual
    dim3 gwo(D_SZ / 128, N_TOK / 128);        // (4, 256)
    gemm_tc<2><<<gwo, 256, SMEM_DYN>>>(pah, pwt + 3 * D_SZ * D_SZ,
                                       bo, nullptr, nullptr, x, py);

    // layernorm
    ln_kernel<<<N_TOK / 8, 256>>>(gamma, beta, out);
}